// round 5
// baseline (speedup 1.0000x reference)
#include <cuda_runtime.h>

// ---------------------------------------------------------------------------
// HiroLRAN: encoder(only t=0) -> chunked linear scan -> decoder
// B=64, T=1024, STATE=256, LATENT=256, ENC=512, ACT=16
// All fp32. Big GEMMs use packed fma.rn.f32x2 (full-rate fp32 on sm_103a).
// ---------------------------------------------------------------------------

#define Bsz 64
#define Tt 1024
#define Din 288
#define LAT 256
#define ENCD 512
#define CHUNK 32
#define NCHUNK 32
#define NROWS (Bsz * Tt)   // 65536

// scratch (device globals: no allocations allowed)
__device__ float g_ZB[(size_t)NROWS * LAT];       // 64 MB: Bu -> b' -> local z -> fixed z
__device__ float g_H1[(size_t)NROWS * ENCD];      // 128 MB
__device__ float g_H2[(size_t)NROWS * ENCD];      // 128 MB
__device__ float g_Apow[33 * LAT * LAT];          // A^1..A^32 (index 0 unused)
__device__ float g_carry[NCHUNK * Bsz * LAT];     // per-chunk carries
__device__ float g_h1e[Bsz * ENCD];
__device__ float g_h2e[Bsz * ENCD];
__device__ float g_z0[Bsz * LAT];

// ---- packed f32x2 helpers -------------------------------------------------
__device__ __forceinline__ unsigned long long pk2(float lo, float hi) {
    unsigned long long r;
    asm("mov.b64 %0, {%1, %2};" : "=l"(r) : "f"(lo), "f"(hi));
    return r;
}
__device__ __forceinline__ void upk2(unsigned long long v, float& lo, float& hi) {
    asm("mov.b64 {%0, %1}, %2;" : "=f"(lo), "=f"(hi) : "l"(v));
}
__device__ __forceinline__ void fma2(unsigned long long& d, unsigned long long a,
                                     unsigned long long b) {
    asm("fma.rn.f32x2 %0, %1, %2, %0;" : "+l"(d) : "l"(a), "l"(b));
}

// ---------------------------------------------------------------------------
// Generic GEMM: C[M,N] = act(A[M,K] (row stride lda) @ W[K,N] + bias[N])
// 128x128 block tile, BK=8, 8x8 per thread, 256 threads, f32x2 inner.
// Requires N % 128 == 0, K % 8 == 0. M arbitrary.
// ---------------------------------------------------------------------------
__global__ __launch_bounds__(256, 2)
void gemm_bias_act(const float* __restrict__ A, long long lda,
                   const float* __restrict__ W,
                   const float* __restrict__ bias,
                   float* __restrict__ C,
                   int M, int N, int K, int act)
{
    __shared__ float As[8][128];
    __shared__ float Ws[8][128];
    const int tid  = threadIdx.x;
    const int crow = blockIdx.y * 128;
    const int ccol = blockIdx.x * 128;
    const int aRow = tid >> 1;
    const int aCol = (tid & 1) * 4;
    const int wRow = tid >> 5;
    const int wCol = (tid & 31) * 4;
    const int ty   = tid >> 4;
    const int tx   = tid & 15;

    unsigned long long acc2[8][4];
#pragma unroll
    for (int i = 0; i < 8; i++)
#pragma unroll
        for (int j = 0; j < 4; j++) acc2[i][j] = 0ull;

    for (int k0 = 0; k0 < K; k0 += 8) {
        float4 av;
        if (crow + aRow < M)
            av = *reinterpret_cast<const float4*>(A + (size_t)(crow + aRow) * lda + k0 + aCol);
        else
            av = make_float4(0.f, 0.f, 0.f, 0.f);
        As[aCol + 0][aRow] = av.x;
        As[aCol + 1][aRow] = av.y;
        As[aCol + 2][aRow] = av.z;
        As[aCol + 3][aRow] = av.w;
        *reinterpret_cast<float4*>(&Ws[wRow][wCol]) =
            *reinterpret_cast<const float4*>(W + (size_t)(k0 + wRow) * N + ccol + wCol);
        __syncthreads();
#pragma unroll
        for (int k = 0; k < 8; k++) {
            const unsigned long long* wp =
                reinterpret_cast<const unsigned long long*>(&Ws[k][tx * 8]);
            unsigned long long rn0 = wp[0], rn1 = wp[1], rn2 = wp[2], rn3 = wp[3];
            float4 a0 = *reinterpret_cast<const float4*>(&As[k][ty * 8]);
            float4 a1 = *reinterpret_cast<const float4*>(&As[k][ty * 8 + 4]);
            float am[8] = {a0.x, a0.y, a0.z, a0.w, a1.x, a1.y, a1.z, a1.w};
#pragma unroll
            for (int i = 0; i < 8; i++) {
                unsigned long long ap = pk2(am[i], am[i]);
                fma2(acc2[i][0], ap, rn0);
                fma2(acc2[i][1], ap, rn1);
                fma2(acc2[i][2], ap, rn2);
                fma2(acc2[i][3], ap, rn3);
            }
        }
        __syncthreads();
    }
    float bv[8];
#pragma unroll
    for (int j = 0; j < 8; j++) bv[j] = bias[ccol + tx * 8 + j];
#pragma unroll
    for (int i = 0; i < 8; i++) {
        int r = crow + ty * 8 + i;
        if (r < M) {
            float o[8];
#pragma unroll
            for (int jp = 0; jp < 4; jp++) upk2(acc2[i][jp], o[2 * jp], o[2 * jp + 1]);
#pragma unroll
            for (int j = 0; j < 8; j++) {
                float v = o[j] + bv[j];
                if (act) v = (v >= 0.f) ? v : 0.01f * v;
                o[j] = v;
            }
            float4* cp = reinterpret_cast<float4*>(C + (size_t)r * N + ccol + tx * 8);
            cp[0] = make_float4(o[0], o[1], o[2], o[3]);
            cp[1] = make_float4(o[4], o[5], o[6], o[7]);
        }
    }
}

// ---------------------------------------------------------------------------
// Bu: g_ZB[b*T + t][j] = sum_k in[b][t][272+k] * Bw[k][j]    (32 rows / block)
// ---------------------------------------------------------------------------
__global__ void bu_kernel(const float* __restrict__ in, const float* __restrict__ Bw)
{
    __shared__ float us[32][16];
    const int tid = threadIdx.x;
    const size_t r0 = (size_t)blockIdx.x * 32;
    float w[16];
#pragma unroll
    for (int k = 0; k < 16; k++) w[k] = Bw[k * 256 + tid];
    // load 32 rows x 16 u values
#pragma unroll
    for (int i = tid; i < 32 * 16; i += 256) {
        int r = i >> 4, k = i & 15;
        us[r][k] = in[(r0 + r) * Din + 272 + k];
    }
    __syncthreads();
#pragma unroll 4
    for (int r = 0; r < 32; r++) {
        float acc = 0.f;
#pragma unroll
        for (int k = 0; k < 16; k++) acc = fmaf(us[r][k], w[k], acc);
        g_ZB[(r0 + r) * 256 + tid] = acc;
    }
}

// ---------------------------------------------------------------------------
// fold: g_ZB[b][t=0][:] += z0[b] @ A   (so b'_0 = Bu_0 + z0@A)
// ---------------------------------------------------------------------------
__global__ void fold_kernel(const float* __restrict__ A)
{
    __shared__ float zs[256];
    const int b = blockIdx.x, j = threadIdx.x;
    zs[j] = g_z0[b * 256 + j];
    __syncthreads();
    float a0 = 0.f, a1 = 0.f, a2 = 0.f, a3 = 0.f;
    for (int k = 0; k < 256; k += 4) {
        a0 = fmaf(zs[k + 0], A[(k + 0) * 256 + j], a0);
        a1 = fmaf(zs[k + 1], A[(k + 1) * 256 + j], a1);
        a2 = fmaf(zs[k + 2], A[(k + 2) * 256 + j], a2);
        a3 = fmaf(zs[k + 3], A[(k + 3) * 256 + j], a3);
    }
    g_ZB[(size_t)b * Tt * 256 + j] += (a0 + a1) + (a2 + a3);
}

// Apow[1] = A ; carry[0] = 0
__global__ void powinit_kernel(const float* __restrict__ A)
{
    const int i = blockIdx.x * 256 + threadIdx.x;
    g_Apow[65536 + i] = A[i];
    if (i < Bsz * 256) g_carry[i] = 0.f;
}

// round with given half: Apow[half+q] = Apow[half] @ Apow[q], q = 1..half
__global__ void pow_round_kernel(int half)
{
    const int q = blockIdx.y + 1;
    const float* S1 = g_Apow + (size_t)half * 65536;
    const float* S2 = g_Apow + (size_t)q * 65536;
    float* D = g_Apow + (size_t)(half + q) * 65536;
    __shared__ float s1[256];
    const int i = blockIdx.x, j = threadIdx.x;
    s1[j] = S1[i * 256 + j];
    __syncthreads();
    float a0 = 0.f, a1 = 0.f, a2 = 0.f, a3 = 0.f;
    for (int k = 0; k < 256; k += 4) {
        a0 = fmaf(s1[k + 0], S2[(k + 0) * 256 + j], a0);
        a1 = fmaf(s1[k + 1], S2[(k + 1) * 256 + j], a1);
        a2 = fmaf(s1[k + 2], S2[(k + 2) * 256 + j], a2);
        a3 = fmaf(s1[k + 3], S2[(k + 3) * 256 + j], a3);
    }
    D[i * 256 + j] = (a0 + a1) + (a2 + a3);
}

// ---------------------------------------------------------------------------
// local step s (s=1..31): for all chunks c, all b:
//   ZB[b][c*32+s] = ZB[b][c*32+s-1] @ A + ZB[b][c*32+s](raw b')
// block = (coltile jb, chunk c); 64(b) x 64(j) tile, K=256
// ---------------------------------------------------------------------------
__global__ __launch_bounds__(256)
void local_step_kernel(const float* __restrict__ A, int s)
{
    __shared__ float Zs[16][64];
    __shared__ float As_[16][64];
    const int c = blockIdx.y;
    const int jb = blockIdx.x * 64;
    const int tid = threadIdx.x;
    const int ty = tid >> 4, tx = tid & 15;
    const int lb = tid >> 2;
    const int lk = (tid & 3) * 4;
    const int lkA = tid >> 4;
    const int ljA = (tid & 15) * 4;
    const int tprev = c * CHUNK + s - 1;
    const float* zprev = g_ZB + ((size_t)lb * Tt + tprev) * 256;
    float acc[4][4] = {};
    for (int k0 = 0; k0 < 256; k0 += 16) {
        float4 zv = *reinterpret_cast<const float4*>(zprev + k0 + lk);
        Zs[lk + 0][lb] = zv.x;
        Zs[lk + 1][lb] = zv.y;
        Zs[lk + 2][lb] = zv.z;
        Zs[lk + 3][lb] = zv.w;
        *reinterpret_cast<float4*>(&As_[lkA][ljA]) =
            *reinterpret_cast<const float4*>(A + (size_t)(k0 + lkA) * 256 + jb + ljA);
        __syncthreads();
#pragma unroll
        for (int k = 0; k < 16; k++) {
            float4 z4 = *reinterpret_cast<const float4*>(&Zs[k][ty * 4]);
            float4 a4 = *reinterpret_cast<const float4*>(&As_[k][tx * 4]);
            float zr[4] = {z4.x, z4.y, z4.z, z4.w};
            float ar[4] = {a4.x, a4.y, a4.z, a4.w};
#pragma unroll
            for (int i = 0; i < 4; i++)
#pragma unroll
                for (int j = 0; j < 4; j++)
                    acc[i][j] = fmaf(zr[i], ar[j], acc[i][j]);
        }
        __syncthreads();
    }
    const int tcur = c * CHUNK + s;
#pragma unroll
    for (int i = 0; i < 4; i++) {
        int b = ty * 4 + i;
        float4* p = reinterpret_cast<float4*>(g_ZB + ((size_t)b * Tt + tcur) * 256 + jb + tx * 4);
        float4 o = *p;
        o.x += acc[i][0]; o.y += acc[i][1]; o.z += acc[i][2]; o.w += acc[i][3];
        *p = o;
    }
}

// carry[c] = carry[c-1] @ A^32 + ZB[:, c*32-1, :]
__global__ void carry_step_kernel(int c)
{
    __shared__ float cp[256];
    const int b = blockIdx.x, j = threadIdx.x;
    cp[j] = g_carry[((size_t)(c - 1) * 64 + b) * 256 + j];
    __syncthreads();
    const float* A32 = g_Apow + (size_t)32 * 65536;
    float a0 = g_ZB[((size_t)b * Tt + c * CHUNK - 1) * 256 + j];
    float a1 = 0.f, a2 = 0.f, a3 = 0.f;
    for (int k = 0; k < 256; k += 4) {
        a0 = fmaf(cp[k + 0], A32[(k + 0) * 256 + j], a0);
        a1 = fmaf(cp[k + 1], A32[(k + 1) * 256 + j], a1);
        a2 = fmaf(cp[k + 2], A32[(k + 2) * 256 + j], a2);
        a3 = fmaf(cp[k + 3], A32[(k + 3) * 256 + j], a3);
    }
    g_carry[((size_t)c * 64 + b) * 256 + j] = ((a0 + a1) + (a2 + a3));
}

// fix: for c=1..31, s=0..31: ZB[b][c*32+s] += carry[c] @ A^{s+1}
__global__ __launch_bounds__(256)
void fix_kernel()
{
    __shared__ float Zs[16][64];
    __shared__ float As_[16][64];
    const int idx = blockIdx.y;            // 0..991
    const int c = (idx >> 5) + 1;          // 1..31
    const int s = idx & 31;                // 0..31
    const int jb = blockIdx.x * 64;
    const int tid = threadIdx.x;
    const int ty = tid >> 4, tx = tid & 15;
    const int lb = tid >> 2;
    const int lk = (tid & 3) * 4;
    const int lkA = tid >> 4;
    const int ljA = (tid & 15) * 4;
    const float* A = g_Apow + (size_t)(s + 1) * 65536;
    const float* cy = g_carry + ((size_t)c * 64 + lb) * 256;
    float acc[4][4] = {};
    for (int k0 = 0; k0 < 256; k0 += 16) {
        float4 zv = *reinterpret_cast<const float4*>(cy + k0 + lk);
        Zs[lk + 0][lb] = zv.x;
        Zs[lk + 1][lb] = zv.y;
        Zs[lk + 2][lb] = zv.z;
        Zs[lk + 3][lb] = zv.w;
        *reinterpret_cast<float4*>(&As_[lkA][ljA]) =
            *reinterpret_cast<const float4*>(A + (size_t)(k0 + lkA) * 256 + jb + ljA);
        __syncthreads();
#pragma unroll
        for (int k = 0; k < 16; k++) {
            float4 z4 = *reinterpret_cast<const float4*>(&Zs[k][ty * 4]);
            float4 a4 = *reinterpret_cast<const float4*>(&As_[k][tx * 4]);
            float zr[4] = {z4.x, z4.y, z4.z, z4.w};
            float ar[4] = {a4.x, a4.y, a4.z, a4.w};
#pragma unroll
            for (int i = 0; i < 4; i++)
#pragma unroll
                for (int j = 0; j < 4; j++)
                    acc[i][j] = fmaf(zr[i], ar[j], acc[i][j]);
        }
        __syncthreads();
    }
    const int t = c * CHUNK + s;
#pragma unroll
    for (int i = 0; i < 4; i++) {
        int b = ty * 4 + i;
        float4* p = reinterpret_cast<float4*>(g_ZB + ((size_t)b * Tt + t) * 256 + jb + tx * 4);
        float4 o = *p;
        o.x += acc[i][0]; o.y += acc[i][1]; o.z += acc[i][2]; o.w += acc[i][3];
        *p = o;
    }
}

// ---------------------------------------------------------------------------
extern "C" void kernel_launch(void* const* d_in, const int* in_sizes, int n_in,
                              void* d_out, int out_size)
{
    const float* in  = (const float*)d_in[0];
    const float* ew1 = (const float*)d_in[1];
    const float* eb1 = (const float*)d_in[2];
    const float* ew2 = (const float*)d_in[3];
    const float* eb2 = (const float*)d_in[4];
    const float* ew3 = (const float*)d_in[5];
    const float* eb3 = (const float*)d_in[6];
    const float* Aw  = (const float*)d_in[7];
    const float* Bw  = (const float*)d_in[8];
    const float* dw1 = (const float*)d_in[9];
    const float* db1 = (const float*)d_in[10];
    const float* dw2 = (const float*)d_in[11];
    const float* db2 = (const float*)d_in[12];
    const float* dw3 = (const float*)d_in[13];
    const float* db3 = (const float*)d_in[14];
    float* out = (float*)d_out;

    void *pzb, *ph1, *ph2, *ph1e, *ph2e, *pz0;
    cudaGetSymbolAddress(&pzb, g_ZB);
    cudaGetSymbolAddress(&ph1, g_H1);
    cudaGetSymbolAddress(&ph2, g_H2);
    cudaGetSymbolAddress(&ph1e, g_h1e);
    cudaGetSymbolAddress(&ph2e, g_h2e);
    cudaGetSymbolAddress(&pz0, g_z0);
    float* zb  = (float*)pzb;
    float* h1  = (float*)ph1;
    float* h2  = (float*)ph2;
    float* h1e = (float*)ph1e;
    float* h2e = (float*)ph2e;
    float* z0  = (float*)pz0;

    // Bu for all t (writes all of g_ZB)
    bu_kernel<<<NROWS / 32, 256>>>(in, Bw);

    // encoder at t=0 only (rows of padded_input at stride T*Din)
    gemm_bias_act<<<dim3(ENCD / 128, 1), 256>>>(in, (long long)Tt * Din, ew1, eb1, h1e,
                                                Bsz, ENCD, 256, 1);
    gemm_bias_act<<<dim3(ENCD / 128, 1), 256>>>(h1e, ENCD, ew2, eb2, h2e,
                                                Bsz, ENCD, ENCD, 1);
    gemm_bias_act<<<dim3(LAT / 128, 1), 256>>>(h2e, ENCD, ew3, eb3, z0,
                                               Bsz, LAT, ENCD, 1);
    // fold z0 into b'_0
    fold_kernel<<<64, 256>>>(Aw);

    // powers A^1..A^32 (log-depth doubling), zero carry[0]
    powinit_kernel<<<256, 256>>>(Aw);
    for (int half = 1; half <= 16; half <<= 1)
        pow_round_kernel<<<dim3(256, half), 256>>>(half);

    // chunk-local scan (32 chunks in parallel, 31 sequential steps)
    for (int s = 1; s < CHUNK; s++)
        local_step_kernel<<<dim3(4, NCHUNK), 256>>>(Aw, s);

    // carry chain across chunks
    for (int c = 1; c < NCHUNK; c++)
        carry_step_kernel<<<64, 256>>>(c);

    // apply carries to chunks 1..31
    fix_kernel<<<dim3(4, (NCHUNK - 1) * CHUNK), 256>>>();

    // decoder (the big GEMMs)
    gemm_bias_act<<<dim3(ENCD / 128, NROWS / 128), 256>>>(zb, LAT, dw1, db1, h1,
                                                          NROWS, ENCD, LAT, 1);
    gemm_bias_act<<<dim3(ENCD / 128, NROWS / 128), 256>>>(h1, ENCD, dw2, db2, h2,
                                                          NROWS, ENCD, ENCD, 1);
    gemm_bias_act<<<dim3(LAT / 128, NROWS / 128), 256>>>(h2, ENCD, dw3, db3, out,
                                                         NROWS, LAT, ENCD, 0);
}

// round 6
// speedup vs baseline: 1.1991x; 1.1991x over previous
#include <cuda_runtime.h>
#include <cstdint>

// ---------------------------------------------------------------------------
// HiroLRAN: encoder(t=0 only) -> chunked linear scan -> decoder
// B=64, T=1024, STATE=256, LATENT=256, ENC=512, ACT=16.  All fp32.
// ---------------------------------------------------------------------------

#define Bsz 64
#define Tt 1024
#define Din 288
#define LAT 256
#define ENCD 512
#define CHUNK 32
#define NCHUNK 32
#define NROWS (Bsz * Tt)   // 65536

// scratch (device globals: no allocations allowed)
__device__ float g_ZB[(size_t)NROWS * LAT];
__device__ float g_H1[(size_t)NROWS * ENCD];
__device__ float g_H2[(size_t)NROWS * ENCD];
__device__ float g_Apow[33 * LAT * LAT];        // A^1..A^32 at idx 1..32
__device__ float g_carry[NCHUNK * Bsz * LAT];
__device__ float g_h1e[Bsz * ENCD];
__device__ float g_h2e[Bsz * ENCD];
__device__ float g_z0[Bsz * LAT];

typedef unsigned long long ull;

// ---- packed f32x2 helpers -------------------------------------------------
__device__ __forceinline__ ull pk2(float lo, float hi) {
    ull r; asm("mov.b64 %0, {%1, %2};" : "=l"(r) : "f"(lo), "f"(hi)); return r;
}
__device__ __forceinline__ void upk2(ull v, float& lo, float& hi) {
    asm("mov.b64 {%0, %1}, %2;" : "=f"(lo), "=f"(hi) : "l"(v));
}
__device__ __forceinline__ void fma2(ull& d, ull a, ull b) {
    asm("fma.rn.f32x2 %0, %1, %2, %0;" : "+l"(d) : "l"(a), "l"(b));
}
__device__ __forceinline__ void cpa16(void* smem_dst, const void* gsrc) {
    uint32_t s = (uint32_t)__cvta_generic_to_shared(smem_dst);
    asm volatile("cp.async.ca.shared.global [%0], [%1], 16;\n" :: "r"(s), "l"(gsrc));
}
__device__ __forceinline__ void cpa_commit() {
    asm volatile("cp.async.commit_group;\n");
}
__device__ __forceinline__ void cpa_wait0() {
    asm volatile("cp.async.wait_group 0;\n" ::: "memory");
}

// ---------------------------------------------------------------------------
// Pipelined 128x128 GEMM, BK=8, 256 threads, 8x8 per thread (2x2 quadrants),
// f32x2 accumulation, cp.async double buffer on W, reg double buffer on A.
// MODE 0: C = act(A@W + bias)   (row-major, ldc=N; requires N%128==0, K%8==0)
// MODE 1: fix scatter: rows index carry (c,b), cols index (s,j) of
//         Wbig = [A^1|...|A^32]; output += into g_ZB[b][c*32+s][j].
// ---------------------------------------------------------------------------
template<int MODE, int ACT>
__global__ __launch_bounds__(256, 2)
void gemm_pipe(const float* __restrict__ A, long long lda,
               const float* __restrict__ W,
               const float* __restrict__ bias,
               float* __restrict__ C,
               int M, int N, int K)
{
    __shared__ __align__(16) float As[2][8][128];
    __shared__ __align__(16) float Ws[2][8][128];
    const int tid  = threadIdx.x;
    const int crow = blockIdx.y * 128;
    const int ccol = blockIdx.x * 128;
    const int aRow = tid >> 1;
    const int aCol = (tid & 1) * 4;
    const int wRow = tid >> 5;
    const int wCol = (tid & 31) * 4;
    const int ty   = tid >> 4;
    const int tx   = tid & 15;

    const float* Wt;
    long long ldw;
    if (MODE == 1) { Wt = W + (size_t)(ccol >> 8) * 65536 + (ccol & 255); ldw = 256; }
    else           { Wt = W + ccol; ldw = N; }

    ull acc[8][4];
#pragma unroll
    for (int i = 0; i < 8; i++)
#pragma unroll
        for (int j = 0; j < 4; j++) acc[i][j] = 0ull;

    // prologue: tile 0
    {
        int r = crow + aRow;
        float4 av = make_float4(0.f, 0.f, 0.f, 0.f);
        if (r < M) av = *reinterpret_cast<const float4*>(A + (size_t)r * lda + aCol);
        As[0][aCol + 0][aRow] = av.x;
        As[0][aCol + 1][aRow] = av.y;
        As[0][aCol + 2][aRow] = av.z;
        As[0][aCol + 3][aRow] = av.w;
        cpa16(&Ws[0][wRow][wCol], Wt + (size_t)wRow * ldw + wCol);
        cpa_commit();
        cpa_wait0();
        __syncthreads();
    }

    int buf = 0;
    for (int k0 = 0; k0 < K; k0 += 8) {
        const bool next = (k0 + 8) < K;
        float4 av;
        if (next) {
            int r = crow + aRow;
            av = make_float4(0.f, 0.f, 0.f, 0.f);
            if (r < M)
                av = *reinterpret_cast<const float4*>(A + (size_t)r * lda + (k0 + 8) + aCol);
            cpa16(&Ws[buf ^ 1][wRow][wCol], Wt + (size_t)(k0 + 8 + wRow) * ldw + wCol);
            cpa_commit();
        }
#pragma unroll
        for (int k = 0; k < 8; k++) {
            float4 alo = *reinterpret_cast<const float4*>(&As[buf][k][ty * 4]);
            float4 ahi = *reinterpret_cast<const float4*>(&As[buf][k][64 + ty * 4]);
            ulonglong2 wlo = *reinterpret_cast<const ulonglong2*>(&Ws[buf][k][tx * 4]);
            ulonglong2 whi = *reinterpret_cast<const ulonglong2*>(&Ws[buf][k][64 + tx * 4]);
            float al[4] = {alo.x, alo.y, alo.z, alo.w};
            float ah[4] = {ahi.x, ahi.y, ahi.z, ahi.w};
#pragma unroll
            for (int i = 0; i < 4; i++) {
                ull ap = pk2(al[i], al[i]);
                fma2(acc[i][0], ap, wlo.x);
                fma2(acc[i][1], ap, wlo.y);
                fma2(acc[i][2], ap, whi.x);
                fma2(acc[i][3], ap, whi.y);
            }
#pragma unroll
            for (int i = 0; i < 4; i++) {
                ull ap = pk2(ah[i], ah[i]);
                fma2(acc[4 + i][0], ap, wlo.x);
                fma2(acc[4 + i][1], ap, wlo.y);
                fma2(acc[4 + i][2], ap, whi.x);
                fma2(acc[4 + i][3], ap, whi.y);
            }
        }
        if (next) {
            As[buf ^ 1][aCol + 0][aRow] = av.x;
            As[buf ^ 1][aCol + 1][aRow] = av.y;
            As[buf ^ 1][aCol + 2][aRow] = av.z;
            As[buf ^ 1][aCol + 3][aRow] = av.w;
        }
        cpa_wait0();
        __syncthreads();
        buf ^= 1;
    }

    // epilogue
    float blo[4], bhi[4];
    if (MODE == 0) {
#pragma unroll
        for (int j = 0; j < 4; j++) {
            blo[j] = bias[ccol + tx * 4 + j];
            bhi[j] = bias[ccol + 64 + tx * 4 + j];
        }
    }
#pragma unroll
    for (int i = 0; i < 8; i++) {
        const int rr = (i < 4) ? (ty * 4 + i) : (64 + ty * 4 + (i - 4));
        const int r = crow + rr;
        if (r >= M) continue;
        float o[8];
        upk2(acc[i][0], o[0], o[1]);
        upk2(acc[i][1], o[2], o[3]);
        upk2(acc[i][2], o[4], o[5]);
        upk2(acc[i][3], o[6], o[7]);
        if (MODE == 0) {
#pragma unroll
            for (int j = 0; j < 4; j++) {
                float v = o[j] + blo[j];
                if (ACT) v = (v >= 0.f) ? v : 0.01f * v;
                o[j] = v;
                float w = o[4 + j] + bhi[j];
                if (ACT) w = (w >= 0.f) ? w : 0.01f * w;
                o[4 + j] = w;
            }
            float4* p0 = reinterpret_cast<float4*>(C + (size_t)r * N + ccol + tx * 4);
            float4* p1 = reinterpret_cast<float4*>(C + (size_t)r * N + ccol + 64 + tx * 4);
            *p0 = make_float4(o[0], o[1], o[2], o[3]);
            *p1 = make_float4(o[4], o[5], o[6], o[7]);
        } else {
            const int c = (r >> 6) + 1;
            const int b = r & 63;
            const int col0 = ccol + tx * 4;
            const int s = col0 >> 8;
            const int t = c * 32 + s;
            const int j0 = col0 & 255;
            const int j1 = (ccol + 64 + tx * 4) & 255;
            float4* p0 = reinterpret_cast<float4*>(&g_ZB[((size_t)b * Tt + t) * 256 + j0]);
            float4* p1 = reinterpret_cast<float4*>(&g_ZB[((size_t)b * Tt + t) * 256 + j1]);
            float4 v0 = *p0, v1 = *p1;
            v0.x += o[0]; v0.y += o[1]; v0.z += o[2]; v0.w += o[3];
            v1.x += o[4]; v1.y += o[5]; v1.z += o[6]; v1.w += o[7];
            *p0 = v0; *p1 = v1;
        }
    }
}

// ---------------------------------------------------------------------------
// Small-M GEMM for the encoder: M=64, 64x64 col tiles, grid = N/64.
// ---------------------------------------------------------------------------
__global__ __launch_bounds__(256)
void gemm_m64(const float* __restrict__ A, long long lda,
              const float* __restrict__ W,
              const float* __restrict__ bias,
              float* __restrict__ C,
              int N, int K, int act)
{
    __shared__ __align__(16) float As[2][16][64];
    __shared__ __align__(16) float Ws[2][16][64];
    const int tid  = threadIdx.x;
    const int ccol = blockIdx.x * 64;
    const int ar = tid >> 2, ak = (tid & 3) * 4;
    const int wr = tid >> 4, wc = (tid & 15) * 4;
    const int ty = tid >> 4, tx = tid & 15;
    float acc[4][4] = {};

    float4 av = *reinterpret_cast<const float4*>(A + (size_t)ar * lda + ak);
    float4 wv = *reinterpret_cast<const float4*>(W + (size_t)wr * N + ccol + wc);
    As[0][ak + 0][ar] = av.x; As[0][ak + 1][ar] = av.y;
    As[0][ak + 2][ar] = av.z; As[0][ak + 3][ar] = av.w;
    *reinterpret_cast<float4*>(&Ws[0][wr][wc]) = wv;
    __syncthreads();

    int buf = 0;
    for (int k0 = 0; k0 < K; k0 += 16) {
        const bool next = (k0 + 16) < K;
        if (next) {
            av = *reinterpret_cast<const float4*>(A + (size_t)ar * lda + k0 + 16 + ak);
            wv = *reinterpret_cast<const float4*>(W + (size_t)(k0 + 16 + wr) * N + ccol + wc);
        }
#pragma unroll
        for (int k = 0; k < 16; k++) {
            float4 a4 = *reinterpret_cast<const float4*>(&As[buf][k][ty * 4]);
            float4 w4 = *reinterpret_cast<const float4*>(&Ws[buf][k][tx * 4]);
            float ar_[4] = {a4.x, a4.y, a4.z, a4.w};
            float wr_[4] = {w4.x, w4.y, w4.z, w4.w};
#pragma unroll
            for (int i = 0; i < 4; i++)
#pragma unroll
                for (int j = 0; j < 4; j++)
                    acc[i][j] = fmaf(ar_[i], wr_[j], acc[i][j]);
        }
        if (next) {
            As[buf ^ 1][ak + 0][ar] = av.x; As[buf ^ 1][ak + 1][ar] = av.y;
            As[buf ^ 1][ak + 2][ar] = av.z; As[buf ^ 1][ak + 3][ar] = av.w;
            *reinterpret_cast<float4*>(&Ws[buf ^ 1][wr][wc]) = wv;
        }
        __syncthreads();
        buf ^= 1;
    }
    float b4[4];
#pragma unroll
    for (int j = 0; j < 4; j++) b4[j] = bias[ccol + tx * 4 + j];
#pragma unroll
    for (int i = 0; i < 4; i++) {
        float o[4];
#pragma unroll
        for (int j = 0; j < 4; j++) {
            float v = acc[i][j] + b4[j];
            if (act) v = (v >= 0.f) ? v : 0.01f * v;
            o[j] = v;
        }
        *reinterpret_cast<float4*>(C + (size_t)(ty * 4 + i) * N + ccol + tx * 4) =
            make_float4(o[0], o[1], o[2], o[3]);
    }
}

// ---------------------------------------------------------------------------
// Bu: g_ZB[b*T + t][j] = sum_k in[b][t][272+k] * Bw[k][j]
// ---------------------------------------------------------------------------
__global__ void bu_kernel(const float* __restrict__ in, const float* __restrict__ Bw)
{
    __shared__ float us[32][16];
    const int tid = threadIdx.x;
    const size_t r0 = (size_t)blockIdx.x * 32;
    float w[16];
#pragma unroll
    for (int k = 0; k < 16; k++) w[k] = Bw[k * 256 + tid];
#pragma unroll
    for (int i = tid; i < 32 * 16; i += 256) {
        int r = i >> 4, k = i & 15;
        us[r][k] = in[(r0 + r) * Din + 272 + k];
    }
    __syncthreads();
#pragma unroll 4
    for (int r = 0; r < 32; r++) {
        float acc = 0.f;
#pragma unroll
        for (int k = 0; k < 16; k++) acc = fmaf(us[r][k], w[k], acc);
        g_ZB[(r0 + r) * 256 + tid] = acc;
    }
}

// fold: g_ZB[b][0][:] += z0[b] @ A
__global__ void fold_kernel(const float* __restrict__ A)
{
    __shared__ float zs[256];
    const int b = blockIdx.x, j = threadIdx.x;
    zs[j] = g_z0[b * 256 + j];
    __syncthreads();
    float a0 = 0.f, a1 = 0.f, a2 = 0.f, a3 = 0.f;
    for (int k = 0; k < 256; k += 4) {
        a0 = fmaf(zs[k + 0], A[(k + 0) * 256 + j], a0);
        a1 = fmaf(zs[k + 1], A[(k + 1) * 256 + j], a1);
        a2 = fmaf(zs[k + 2], A[(k + 2) * 256 + j], a2);
        a3 = fmaf(zs[k + 3], A[(k + 3) * 256 + j], a3);
    }
    g_ZB[(size_t)b * Tt * 256 + j] += (a0 + a1) + (a2 + a3);
}

// Apow[1] = A
__global__ void powinit_kernel(const float* __restrict__ A)
{
    const int i = blockIdx.x * 256 + threadIdx.x;
    g_Apow[65536 + i] = A[i];
}

// Apow[half+q] = Apow[half] @ Apow[q], q = blockIdx.z+1. Tiled 64x64.
__global__ __launch_bounds__(256)
void pow_gemm(int half)
{
    const int q = blockIdx.z + 1;
    const float* S1 = g_Apow + (size_t)half * 65536;
    const float* S2 = g_Apow + (size_t)q * 65536;
    float* D = g_Apow + (size_t)(half + q) * 65536;
    const int ib = blockIdx.y * 64, jb = blockIdx.x * 64;
    __shared__ __align__(16) float As[16][64];
    __shared__ __align__(16) float Bs[16][64];
    const int tid = threadIdx.x;
    const int ar = tid >> 2, ak = (tid & 3) * 4;
    const int wr = tid >> 4, wc = (tid & 15) * 4;
    const int ty = tid >> 4, tx = tid & 15;
    float acc[4][4] = {};
    for (int k0 = 0; k0 < 256; k0 += 16) {
        float4 av = *reinterpret_cast<const float4*>(S1 + (size_t)(ib + ar) * 256 + k0 + ak);
        As[ak + 0][ar] = av.x; As[ak + 1][ar] = av.y;
        As[ak + 2][ar] = av.z; As[ak + 3][ar] = av.w;
        *reinterpret_cast<float4*>(&Bs[wr][wc]) =
            *reinterpret_cast<const float4*>(S2 + (size_t)(k0 + wr) * 256 + jb + wc);
        __syncthreads();
#pragma unroll
        for (int k = 0; k < 16; k++) {
            float4 a4 = *reinterpret_cast<const float4*>(&As[k][ty * 4]);
            float4 w4 = *reinterpret_cast<const float4*>(&Bs[k][tx * 4]);
            float ar_[4] = {a4.x, a4.y, a4.z, a4.w};
            float wr_[4] = {w4.x, w4.y, w4.z, w4.w};
#pragma unroll
            for (int i = 0; i < 4; i++)
#pragma unroll
                for (int j = 0; j < 4; j++)
                    acc[i][j] = fmaf(ar_[i], wr_[j], acc[i][j]);
        }
        __syncthreads();
    }
#pragma unroll
    for (int i = 0; i < 4; i++)
        *reinterpret_cast<float4*>(D + (size_t)(ib + ty * 4 + i) * 256 + jb + tx * 4) =
            make_float4(acc[i][0], acc[i][1], acc[i][2], acc[i][3]);
}

// ---------------------------------------------------------------------------
// local step s: ZB[b][c*32+s] += ZB[b][c*32+s-1] @ A  (pipelined 64x64 tiles)
// ---------------------------------------------------------------------------
__global__ __launch_bounds__(256)
void local_step2(const float* __restrict__ A, int s)
{
    __shared__ __align__(16) float Zs[2][16][64];
    __shared__ __align__(16) float As_[2][16][64];
    const int c = blockIdx.y;
    const int jb = blockIdx.x * 64;
    const int tid = threadIdx.x;
    const int ty = tid >> 4, tx = tid & 15;
    const int zr = tid >> 2, zk = (tid & 3) * 4;
    const int ar = tid >> 4, ac = (tid & 15) * 4;
    const int tprev = c * CHUNK + s - 1;
    const float* zprev = g_ZB + ((size_t)zr * Tt + tprev) * 256;
    float acc[4][4] = {};

    // prologue
    {
        float4 zv = *reinterpret_cast<const float4*>(zprev + zk);
        Zs[0][zk + 0][zr] = zv.x; Zs[0][zk + 1][zr] = zv.y;
        Zs[0][zk + 2][zr] = zv.z; Zs[0][zk + 3][zr] = zv.w;
        cpa16(&As_[0][ar][ac], A + (size_t)ar * 256 + jb + ac);
        cpa_commit();
        cpa_wait0();
        __syncthreads();
    }
    int buf = 0;
    for (int k0 = 0; k0 < 256; k0 += 16) {
        const bool next = (k0 + 16) < 256;
        float4 zv;
        if (next) {
            zv = *reinterpret_cast<const float4*>(zprev + k0 + 16 + zk);
            cpa16(&As_[buf ^ 1][ar][ac], A + (size_t)(k0 + 16 + ar) * 256 + jb + ac);
            cpa_commit();
        }
#pragma unroll
        for (int k = 0; k < 16; k++) {
            float4 z4 = *reinterpret_cast<const float4*>(&Zs[buf][k][ty * 4]);
            float4 a4 = *reinterpret_cast<const float4*>(&As_[buf][k][tx * 4]);
            float zrr[4] = {z4.x, z4.y, z4.z, z4.w};
            float arr[4] = {a4.x, a4.y, a4.z, a4.w};
#pragma unroll
            for (int i = 0; i < 4; i++)
#pragma unroll
                for (int j = 0; j < 4; j++)
                    acc[i][j] = fmaf(zrr[i], arr[j], acc[i][j]);
        }
        if (next) {
            Zs[buf ^ 1][zk + 0][zr] = zv.x; Zs[buf ^ 1][zk + 1][zr] = zv.y;
            Zs[buf ^ 1][zk + 2][zr] = zv.z; Zs[buf ^ 1][zk + 3][zr] = zv.w;
        }
        cpa_wait0();
        __syncthreads();
        buf ^= 1;
    }
    const int tcur = c * CHUNK + s;
#pragma unroll
    for (int i = 0; i < 4; i++) {
        float4* p = reinterpret_cast<float4*>(
            g_ZB + ((size_t)(ty * 4 + i) * Tt + tcur) * 256 + jb + tx * 4);
        float4 o = *p;
        o.x += acc[i][0]; o.y += acc[i][1]; o.z += acc[i][2]; o.w += acc[i][3];
        *p = o;
    }
}

// ---------------------------------------------------------------------------
// carry chain, single launch: 32 blocks, 2 batches each.
// carry[c] = carry[c-1] @ A^32 + ZB[:, c*32-1, :]
// ---------------------------------------------------------------------------
__global__ void carry_chain()
{
    const int bg = blockIdx.x * 2;
    const int j = threadIdx.x;
    __shared__ float cp0[256], cp1[256];
    cp0[j] = 0.f; cp1[j] = 0.f;
    __syncthreads();
    const float* A32 = g_Apow + (size_t)32 * 65536;
    for (int c = 1; c < NCHUNK; c++) {
        float a0 = g_ZB[((size_t)bg * Tt + c * CHUNK - 1) * 256 + j];
        float a1 = g_ZB[((size_t)(bg + 1) * Tt + c * CHUNK - 1) * 256 + j];
#pragma unroll 4
        for (int k = 0; k < 256; k++) {
            float w = A32[(size_t)k * 256 + j];
            a0 = fmaf(cp0[k], w, a0);
            a1 = fmaf(cp1[k], w, a1);
        }
        __syncthreads();
        cp0[j] = a0; cp1[j] = a1;
        g_carry[((size_t)c * 64 + bg) * 256 + j] = a0;
        g_carry[((size_t)c * 64 + bg + 1) * 256 + j] = a1;
        __syncthreads();
    }
}

// ---------------------------------------------------------------------------
extern "C" void kernel_launch(void* const* d_in, const int* in_sizes, int n_in,
                              void* d_out, int out_size)
{
    const float* in  = (const float*)d_in[0];
    const float* ew1 = (const float*)d_in[1];
    const float* eb1 = (const float*)d_in[2];
    const float* ew2 = (const float*)d_in[3];
    const float* eb2 = (const float*)d_in[4];
    const float* ew3 = (const float*)d_in[5];
    const float* eb3 = (const float*)d_in[6];
    const float* Aw  = (const float*)d_in[7];
    const float* Bw  = (const float*)d_in[8];
    const float* dw1 = (const float*)d_in[9];
    const float* db1 = (const float*)d_in[10];
    const float* dw2 = (const float*)d_in[11];
    const float* db2 = (const float*)d_in[12];
    const float* dw3 = (const float*)d_in[13];
    const float* db3 = (const float*)d_in[14];
    float* out = (float*)d_out;

    void *pzb, *ph1, *ph2, *ph1e, *ph2e, *pz0, *pcar, *papw;
    cudaGetSymbolAddress(&pzb, g_ZB);
    cudaGetSymbolAddress(&ph1, g_H1);
    cudaGetSymbolAddress(&ph2, g_H2);
    cudaGetSymbolAddress(&ph1e, g_h1e);
    cudaGetSymbolAddress(&ph2e, g_h2e);
    cudaGetSymbolAddress(&pz0, g_z0);
    cudaGetSymbolAddress(&pcar, g_carry);
    cudaGetSymbolAddress(&papw, g_Apow);
    float* zb   = (float*)pzb;
    float* h1   = (float*)ph1;
    float* h2   = (float*)ph2;
    float* h1e  = (float*)ph1e;
    float* h2e  = (float*)ph2e;
    float* z0   = (float*)pz0;
    float* car1 = (float*)pcar + (size_t)64 * 256;       // carry rows c=1..31
    float* apw1 = (float*)papw + 65536;                  // A^1 base

    // Bu for all t (writes all of g_ZB)
    bu_kernel<<<NROWS / 32, 256>>>(in, Bw);

    // encoder at t=0 only
    gemm_m64<<<ENCD / 64, 256>>>(in, (long long)Tt * Din, ew1, eb1, h1e, ENCD, 256, 1);
    gemm_m64<<<ENCD / 64, 256>>>(h1e, ENCD, ew2, eb2, h2e, ENCD, ENCD, 1);
    gemm_m64<<<LAT / 64, 256>>>(h2e, ENCD, ew3, eb3, z0, LAT, ENCD, 1);
    fold_kernel<<<64, 256>>>(Aw);

    // powers A^1..A^32
    powinit_kernel<<<256, 256>>>(Aw);
    for (int half = 1; half <= 16; half <<= 1)
        pow_gemm<<<dim3(4, 4, half), 256>>>(half);

    // chunk-local scan
    for (int s = 1; s < CHUNK; s++)
        local_step2<<<dim3(4, NCHUNK), 256>>>(Aw, s);

    // carry chain (single launch)
    carry_chain<<<32, 256>>>();

    // fix as one GEMM: carry(1984x256) @ [A^1|..|A^32](256x8192), scatter += ZB
    gemm_pipe<1, 0><<<dim3(64, 16), 256>>>(car1, 256, apw1, nullptr, nullptr,
                                           1984, 8192, 256);

    // decoder
    gemm_pipe<0, 1><<<dim3(ENCD / 128, NROWS / 128), 256>>>(zb, LAT, dw1, db1, h1,
                                                            NROWS, ENCD, LAT);
    gemm_pipe<0, 1><<<dim3(ENCD / 128, NROWS / 128), 256>>>(h1, ENCD, dw2, db2, h2,
                                                            NROWS, ENCD, ENCD);
    gemm_pipe<0, 0><<<dim3(LAT / 128, NROWS / 128), 256>>>(h2, ENCD, dw3, db3, out,
                                                           NROWS, LAT, ENCD);
}

// round 8
// speedup vs baseline: 1.5228x; 1.2699x over previous
#include <cuda_runtime.h>
#include <cuda_bf16.h>
#include <cstdint>

// ---------------------------------------------------------------------------
// HiroLRAN: encoder(t=0 only) -> chunked linear scan (fp32) ->
//           decoder on warp-level mma.sync bf16 split-precision MMA.
// B=64, T=1024, STATE=256, LATENT=256, ENC=512, ACT=16.
// ---------------------------------------------------------------------------

#define Bsz 64
#define Tt 1024
#define Din 288
#define LAT 256
#define ENCD 512
#define CHUNK 32
#define NCHUNK 32
#define NROWS (Bsz * Tt)   // 65536
#define PADK 40            // padded K-stride (elements) for ldmatrix tiles

// scratch (device globals: no allocations allowed)
__device__ float g_ZB[(size_t)NROWS * LAT];
__device__ float g_H1[(size_t)NROWS * ENCD];     // aliased: B1 hi|lo bf16
__device__ float g_H2[(size_t)NROWS * ENCD];     // aliased: B2 hi|lo bf16
__device__ float g_Apow[33 * LAT * LAT];
__device__ float g_carry[NCHUNK * Bsz * LAT];
__device__ float g_h1e[Bsz * ENCD];
__device__ float g_h2e[Bsz * ENCD];
__device__ float g_z0[Bsz * LAT];
__device__ __nv_bfloat16 g_AZh[(size_t)NROWS * LAT];
__device__ __nv_bfloat16 g_AZl[(size_t)NROWS * LAT];
__device__ __nv_bfloat16 g_W1h[ENCD * LAT], g_W1l[ENCD * LAT];   // N x K
__device__ __nv_bfloat16 g_W2h[ENCD * ENCD], g_W2l[ENCD * ENCD];
__device__ __nv_bfloat16 g_W3h[LAT * ENCD], g_W3l[LAT * ENCD];

typedef unsigned long long ull;

// ---- packed f32x2 helpers (fp32 path) --------------------------------------
__device__ __forceinline__ ull pk2(float lo, float hi) {
    ull r; asm("mov.b64 %0, {%1, %2};" : "=l"(r) : "f"(lo), "f"(hi)); return r;
}
__device__ __forceinline__ void upk2(ull v, float& lo, float& hi) {
    asm("mov.b64 {%0, %1}, %2;" : "=f"(lo), "=f"(hi) : "l"(v));
}
__device__ __forceinline__ void fma2(ull& d, ull a, ull b) {
    asm("fma.rn.f32x2 %0, %1, %2, %0;" : "+l"(d) : "l"(a), "l"(b));
}
__device__ __forceinline__ void cpa16(void* smem_dst, const void* gsrc) {
    uint32_t s = (uint32_t)__cvta_generic_to_shared(smem_dst);
    asm volatile("cp.async.ca.shared.global [%0], [%1], 16;\n" :: "r"(s), "l"(gsrc));
}
__device__ __forceinline__ void cpa16s(uint32_t saddr, const void* gsrc) {
    asm volatile("cp.async.ca.shared.global [%0], [%1], 16;\n" :: "r"(saddr), "l"(gsrc));
}
__device__ __forceinline__ void cpa_commit() {
    asm volatile("cp.async.commit_group;\n");
}
__device__ __forceinline__ void cpa_wait0() {
    asm volatile("cp.async.wait_group 0;\n" ::: "memory");
}
__device__ __forceinline__ void cpa_wait1() {
    asm volatile("cp.async.wait_group 1;\n" ::: "memory");
}
__device__ __forceinline__ uint32_t smem_u32(const void* p) {
    return (uint32_t)__cvta_generic_to_shared(p);
}

// ---- warp-level mma helpers -------------------------------------------------
__device__ __forceinline__ void ldsm4(uint32_t addr, uint32_t& r0, uint32_t& r1,
                                      uint32_t& r2, uint32_t& r3) {
    asm volatile("ldmatrix.sync.aligned.m8n8.x4.shared.b16 {%0,%1,%2,%3}, [%4];"
                 : "=r"(r0), "=r"(r1), "=r"(r2), "=r"(r3) : "r"(addr));
}
__device__ __forceinline__ void mma16816(float* c, const uint32_t* a,
                                         const uint32_t* b) {
    asm volatile(
        "mma.sync.aligned.m16n8k16.row.col.f32.bf16.bf16.f32 "
        "{%0,%1,%2,%3}, {%4,%5,%6,%7}, {%8,%9}, {%0,%1,%2,%3};"
        : "+f"(c[0]), "+f"(c[1]), "+f"(c[2]), "+f"(c[3])
        : "r"(a[0]), "r"(a[1]), "r"(a[2]), "r"(a[3]), "r"(b[0]), "r"(b[1]));
}

// ---------------------------------------------------------------------------
// mma.sync split-bf16 GEMM: C[M,N] = act(Afull @ Wfull^T + bias)
// A as (Ah,Al) M x K bf16 row-major; W as (Bh,Bl) N x K bf16 row-major.
// 128x128 CTA tile, 8 warps (2x4), warp tile 64x32, BK=32 double-buffered.
// 3 products per k-chunk: Ah*Bh + Ah*Bl + Al*Bh (fp32 accumulate).
// SPLIT=1: epilogue emits hi/lo bf16; SPLIT=0: fp32 out.
// ---------------------------------------------------------------------------
#define STAGE_ELEMS (4 * 128 * PADK)           // 20480 bf16 per stage
#define MMA_SMEM (2 * STAGE_ELEMS * 2)         // 81920 bytes

template<int ACT, int SPLIT>
__global__ __launch_bounds__(256, 1)
void mma_gemm(const __nv_bfloat16* __restrict__ Ah, const __nv_bfloat16* __restrict__ Al,
              const __nv_bfloat16* __restrict__ Bh, const __nv_bfloat16* __restrict__ Bl,
              const float* __restrict__ bias,
              __nv_bfloat16* __restrict__ oHi, __nv_bfloat16* __restrict__ oLo,
              float* __restrict__ oF, int N, int K)
{
    extern __shared__ __align__(16) __nv_bfloat16 smem[];
    const int tid  = threadIdx.x;
    const int warp = tid >> 5;
    const int lane = tid & 31;
    const int crow = blockIdx.y * 128;
    const int ccol = blockIdx.x * 128;
    const int mo = (warp >> 2) * 64;     // warp m offset in tile
    const int no = (warp & 3) * 32;      // warp n offset in tile

    const __nv_bfloat16* gsrc[4] = {
        Ah + (size_t)crow * K, Al + (size_t)crow * K,
        Bh + (size_t)ccol * K, Bl + (size_t)ccol * K };

    // load one BK=32 chunk into stage s (rows padded to PADK)
    auto load_chunk = [&](int s, int kc) {
#pragma unroll
        for (int q = 0; q < 4; q++) {
            const __nv_bfloat16* src = gsrc[q] + kc * 32;
            __nv_bfloat16* dstb = smem + s * STAGE_ELEMS + q * 128 * PADK;
#pragma unroll
            for (int t = 0; t < 2; t++) {
                int g = tid + t * 256;           // 512 granules of 16B
                int row = g >> 2, c = g & 3;
                cpa16s(smem_u32(dstb + row * PADK + c * 8),
                       src + (size_t)row * K + c * 8);
            }
        }
        cpa_commit();
    };

    float acc[4][4][4];
#pragma unroll
    for (int i = 0; i < 4; i++)
#pragma unroll
        for (int j = 0; j < 4; j++)
#pragma unroll
            for (int v = 0; v < 4; v++) acc[i][j][v] = 0.f;

    const int nch = K / 32;
    load_chunk(0, 0);
    load_chunk(1, 1);

    // ldmatrix lane address components
    const int a_rowsel = lane & 15;
    const int a_colsel = (lane >> 4) << 3;             // 0 or 8
    const int b_rowsel = ((lane >> 4) << 3) + (lane & 7);
    const int b_colsel = ((lane >> 3) & 1) << 3;       // 0 or 8

    for (int i = 0; i < nch; i++) {
        const int s = i & 1;
        if (i + 1 < nch) cpa_wait1(); else cpa_wait0();
        __syncthreads();
        const uint32_t stb = smem_u32(smem) + s * STAGE_ELEMS * 2;
        const uint32_t bAh = stb;
        const uint32_t bAl = stb + 128 * PADK * 2;
        const uint32_t bBh = stb + 2 * 128 * PADK * 2;
        const uint32_t bBl = stb + 3 * 128 * PADK * 2;
#pragma unroll
        for (int kk = 0; kk < 2; kk++) {
            const int kc = kk * 16;
            uint32_t a[4][4], b[4][2], bl[4][2];
            // A = Ah fragments (4 m-tiles)
#pragma unroll
            for (int it = 0; it < 4; it++) {
                int row = mo + it * 16 + a_rowsel;
                ldsm4(bAh + (row * PADK + kc + a_colsel) * 2,
                      a[it][0], a[it][1], a[it][2], a[it][3]);
            }
            // B = Bh fragments (4 n-tiles via 2 x ldsm4)
#pragma unroll
            for (int jj = 0; jj < 2; jj++) {
                int row = no + jj * 16 + b_rowsel;
                ldsm4(bBh + (row * PADK + kc + b_colsel) * 2,
                      b[2 * jj][0], b[2 * jj][1], b[2 * jj + 1][0], b[2 * jj + 1][1]);
            }
#pragma unroll
            for (int it = 0; it < 4; it++)
#pragma unroll
                for (int jt = 0; jt < 4; jt++) mma16816(acc[it][jt], a[it], b[jt]);
            // Bl fragments
#pragma unroll
            for (int jj = 0; jj < 2; jj++) {
                int row = no + jj * 16 + b_rowsel;
                ldsm4(bBl + (row * PADK + kc + b_colsel) * 2,
                      bl[2 * jj][0], bl[2 * jj][1], bl[2 * jj + 1][0], bl[2 * jj + 1][1]);
            }
#pragma unroll
            for (int it = 0; it < 4; it++)
#pragma unroll
                for (int jt = 0; jt < 4; jt++) mma16816(acc[it][jt], a[it], bl[jt]);
            // A = Al fragments (reuse a regs)
#pragma unroll
            for (int it = 0; it < 4; it++) {
                int row = mo + it * 16 + a_rowsel;
                ldsm4(bAl + (row * PADK + kc + a_colsel) * 2,
                      a[it][0], a[it][1], a[it][2], a[it][3]);
            }
#pragma unroll
            for (int it = 0; it < 4; it++)
#pragma unroll
                for (int jt = 0; jt < 4; jt++) mma16816(acc[it][jt], a[it], b[jt]);
        }
        __syncthreads();
        if (i + 2 < nch) load_chunk(s, i + 2);
    }

    // epilogue: thread (lane) holds c0,c1 @ (row = lane/4, col = (lane%4)*2),
    // c2,c3 @ row+8, per (m-tile, n-tile).
#pragma unroll
    for (int it = 0; it < 4; it++) {
#pragma unroll
        for (int jt = 0; jt < 4; jt++) {
            const int r0 = crow + mo + it * 16 + (lane >> 2);
            const int gc = ccol + no + jt * 8 + (lane & 3) * 2;
            const float b0 = bias[gc], b1 = bias[gc + 1];
            float v00 = acc[it][jt][0] + b0, v01 = acc[it][jt][1] + b1;
            float v10 = acc[it][jt][2] + b0, v11 = acc[it][jt][3] + b1;
            if (ACT) {
                v00 = (v00 >= 0.f) ? v00 : 0.01f * v00;
                v01 = (v01 >= 0.f) ? v01 : 0.01f * v01;
                v10 = (v10 >= 0.f) ? v10 : 0.01f * v10;
                v11 = (v11 >= 0.f) ? v11 : 0.01f * v11;
            }
            if (SPLIT) {
                __nv_bfloat16 h00 = __float2bfloat16(v00), h01 = __float2bfloat16(v01);
                __nv_bfloat16 h10 = __float2bfloat16(v10), h11 = __float2bfloat16(v11);
                *reinterpret_cast<__nv_bfloat162*>(oHi + (size_t)r0 * N + gc) =
                    __nv_bfloat162(h00, h01);
                *reinterpret_cast<__nv_bfloat162*>(oHi + (size_t)(r0 + 8) * N + gc) =
                    __nv_bfloat162(h10, h11);
                *reinterpret_cast<__nv_bfloat162*>(oLo + (size_t)r0 * N + gc) =
                    __nv_bfloat162(__float2bfloat16(v00 - __bfloat162float(h00)),
                                   __float2bfloat16(v01 - __bfloat162float(h01)));
                *reinterpret_cast<__nv_bfloat162*>(oLo + (size_t)(r0 + 8) * N + gc) =
                    __nv_bfloat162(__float2bfloat16(v10 - __bfloat162float(h10)),
                                   __float2bfloat16(v11 - __bfloat162float(h11)));
            } else {
                *reinterpret_cast<float2*>(oF + (size_t)r0 * N + gc) =
                    make_float2(v00, v01);
                *reinterpret_cast<float2*>(oF + (size_t)(r0 + 8) * N + gc) =
                    make_float2(v10, v11);
            }
        }
    }
}

// split padded fp32 -> (hi, lo) bf16, same layout
__global__ void split_f32(const float* __restrict__ src,
                          __nv_bfloat16* __restrict__ hi,
                          __nv_bfloat16* __restrict__ lo, size_t n)
{
    size_t i = ((size_t)blockIdx.x * blockDim.x + threadIdx.x) * 4;
    if (i >= n) return;
    float4 v = *reinterpret_cast<const float4*>(src + i);
    __nv_bfloat16 h0 = __float2bfloat16(v.x), h1 = __float2bfloat16(v.y);
    __nv_bfloat16 h2 = __float2bfloat16(v.z), h3 = __float2bfloat16(v.w);
    reinterpret_cast<__nv_bfloat162*>(hi + i)[0] = __nv_bfloat162(h0, h1);
    reinterpret_cast<__nv_bfloat162*>(hi + i)[1] = __nv_bfloat162(h2, h3);
    reinterpret_cast<__nv_bfloat162*>(lo + i)[0] = __nv_bfloat162(
        __float2bfloat16(v.x - __bfloat162float(h0)),
        __float2bfloat16(v.y - __bfloat162float(h1)));
    reinterpret_cast<__nv_bfloat162*>(lo + i)[1] = __nv_bfloat162(
        __float2bfloat16(v.z - __bfloat162float(h2)),
        __float2bfloat16(v.w - __bfloat162float(h3)));
}

// split + transpose weights: W (K x N fp32) -> hi/lo (N x K bf16)
__global__ void split_w(const float* __restrict__ W, int K, int N,
                        __nv_bfloat16* __restrict__ hi, __nv_bfloat16* __restrict__ lo)
{
    int idx = blockIdx.x * 256 + threadIdx.x;
    if (idx >= K * N) return;
    int k = idx / N, n = idx % N;
    float v = W[idx];
    __nv_bfloat16 h = __float2bfloat16(v);
    hi[(size_t)n * K + k] = h;
    lo[(size_t)n * K + k] = __float2bfloat16(v - __bfloat162float(h));
}

// ---------------------------------------------------------------------------
// fp32 pipelined GEMM (fix scatter, MODE 1)
// ---------------------------------------------------------------------------
template<int MODE, int ACT>
__global__ __launch_bounds__(256, 2)
void gemm_pipe(const float* __restrict__ A, long long lda,
               const float* __restrict__ W,
               const float* __restrict__ bias,
               float* __restrict__ C,
               int M, int N, int K)
{
    __shared__ __align__(16) float As[2][8][128];
    __shared__ __align__(16) float Ws[2][8][128];
    const int tid  = threadIdx.x;
    const int crow = blockIdx.y * 128;
    const int ccol = blockIdx.x * 128;
    const int aRow = tid >> 1;
    const int aCol = (tid & 1) * 4;
    const int wRow = tid >> 5;
    const int wCol = (tid & 31) * 4;
    const int ty   = tid >> 4;
    const int tx   = tid & 15;

    const float* Wt;
    long long ldw;
    if (MODE == 1) { Wt = W + (size_t)(ccol >> 8) * 65536 + (ccol & 255); ldw = 256; }
    else           { Wt = W + ccol; ldw = N; }

    ull acc[8][4];
#pragma unroll
    for (int i = 0; i < 8; i++)
#pragma unroll
        for (int j = 0; j < 4; j++) acc[i][j] = 0ull;

    {
        int r = crow + aRow;
        float4 av = make_float4(0.f, 0.f, 0.f, 0.f);
        if (r < M) av = *reinterpret_cast<const float4*>(A + (size_t)r * lda + aCol);
        As[0][aCol + 0][aRow] = av.x;
        As[0][aCol + 1][aRow] = av.y;
        As[0][aCol + 2][aRow] = av.z;
        As[0][aCol + 3][aRow] = av.w;
        cpa16(&Ws[0][wRow][wCol], Wt + (size_t)wRow * ldw + wCol);
        cpa_commit();
        cpa_wait0();
        __syncthreads();
    }

    int buf = 0;
    for (int k0 = 0; k0 < K; k0 += 8) {
        const bool next = (k0 + 8) < K;
        float4 av;
        if (next) {
            int r = crow + aRow;
            av = make_float4(0.f, 0.f, 0.f, 0.f);
            if (r < M)
                av = *reinterpret_cast<const float4*>(A + (size_t)r * lda + (k0 + 8) + aCol);
            cpa16(&Ws[buf ^ 1][wRow][wCol], Wt + (size_t)(k0 + 8 + wRow) * ldw + wCol);
            cpa_commit();
        }
#pragma unroll
        for (int k = 0; k < 8; k++) {
            float4 alo = *reinterpret_cast<const float4*>(&As[buf][k][ty * 4]);
            float4 ahi = *reinterpret_cast<const float4*>(&As[buf][k][64 + ty * 4]);
            ulonglong2 wlo = *reinterpret_cast<const ulonglong2*>(&Ws[buf][k][tx * 4]);
            ulonglong2 whi = *reinterpret_cast<const ulonglong2*>(&Ws[buf][k][64 + tx * 4]);
            float al[4] = {alo.x, alo.y, alo.z, alo.w};
            float ah[4] = {ahi.x, ahi.y, ahi.z, ahi.w};
#pragma unroll
            for (int i = 0; i < 4; i++) {
                ull ap = pk2(al[i], al[i]);
                fma2(acc[i][0], ap, wlo.x);
                fma2(acc[i][1], ap, wlo.y);
                fma2(acc[i][2], ap, whi.x);
                fma2(acc[i][3], ap, whi.y);
            }
#pragma unroll
            for (int i = 0; i < 4; i++) {
                ull ap = pk2(ah[i], ah[i]);
                fma2(acc[4 + i][0], ap, wlo.x);
                fma2(acc[4 + i][1], ap, wlo.y);
                fma2(acc[4 + i][2], ap, whi.x);
                fma2(acc[4 + i][3], ap, whi.y);
            }
        }
        if (next) {
            As[buf ^ 1][aCol + 0][aRow] = av.x;
            As[buf ^ 1][aCol + 1][aRow] = av.y;
            As[buf ^ 1][aCol + 2][aRow] = av.z;
            As[buf ^ 1][aCol + 3][aRow] = av.w;
        }
        cpa_wait0();
        __syncthreads();
        buf ^= 1;
    }

    float blo[4], bhi[4];
    if (MODE == 0) {
#pragma unroll
        for (int j = 0; j < 4; j++) {
            blo[j] = bias[ccol + tx * 4 + j];
            bhi[j] = bias[ccol + 64 + tx * 4 + j];
        }
    }
#pragma unroll
    for (int i = 0; i < 8; i++) {
        const int rr = (i < 4) ? (ty * 4 + i) : (64 + ty * 4 + (i - 4));
        const int r = crow + rr;
        if (r >= M) continue;
        float o[8];
        upk2(acc[i][0], o[0], o[1]);
        upk2(acc[i][1], o[2], o[3]);
        upk2(acc[i][2], o[4], o[5]);
        upk2(acc[i][3], o[6], o[7]);
        if (MODE == 0) {
#pragma unroll
            for (int j = 0; j < 4; j++) {
                float v = o[j] + blo[j];
                if (ACT) v = (v >= 0.f) ? v : 0.01f * v;
                o[j] = v;
                float w = o[4 + j] + bhi[j];
                if (ACT) w = (w >= 0.f) ? w : 0.01f * w;
                o[4 + j] = w;
            }
            float4* p0 = reinterpret_cast<float4*>(C + (size_t)r * N + ccol + tx * 4);
            float4* p1 = reinterpret_cast<float4*>(C + (size_t)r * N + ccol + 64 + tx * 4);
            *p0 = make_float4(o[0], o[1], o[2], o[3]);
            *p1 = make_float4(o[4], o[5], o[6], o[7]);
        } else {
            const int c = (r >> 6) + 1;
            const int b = r & 63;
            const int col0 = ccol + tx * 4;
            const int s = col0 >> 8;
            const int t = c * 32 + s;
            const int j0 = col0 & 255;
            const int j1 = (ccol + 64 + tx * 4) & 255;
            float4* p0 = reinterpret_cast<float4*>(&g_ZB[((size_t)b * Tt + t) * 256 + j0]);
            float4* p1 = reinterpret_cast<float4*>(&g_ZB[((size_t)b * Tt + t) * 256 + j1]);
            float4 v0 = *p0, v1 = *p1;
            v0.x += o[0]; v0.y += o[1]; v0.z += o[2]; v0.w += o[3];
            v1.x += o[4]; v1.y += o[5]; v1.z += o[6]; v1.w += o[7];
            *p0 = v0; *p1 = v1;
        }
    }
}

// ---------------------------------------------------------------------------
// Small-M GEMM (encoder, M=64)
// ---------------------------------------------------------------------------
__global__ __launch_bounds__(256)
void gemm_m64(const float* __restrict__ A, long long lda,
              const float* __restrict__ W,
              const float* __restrict__ bias,
              float* __restrict__ C,
              int N, int K, int act)
{
    __shared__ __align__(16) float As[2][16][64];
    __shared__ __align__(16) float Ws[2][16][64];
    const int tid  = threadIdx.x;
    const int ccol = blockIdx.x * 64;
    const int ar = tid >> 2, ak = (tid & 3) * 4;
    const int wr = tid >> 4, wc = (tid & 15) * 4;
    const int ty = tid >> 4, tx = tid & 15;
    float acc[4][4] = {};

    float4 av = *reinterpret_cast<const float4*>(A + (size_t)ar * lda + ak);
    float4 wv = *reinterpret_cast<const float4*>(W + (size_t)wr * N + ccol + wc);
    As[0][ak + 0][ar] = av.x; As[0][ak + 1][ar] = av.y;
    As[0][ak + 2][ar] = av.z; As[0][ak + 3][ar] = av.w;
    *reinterpret_cast<float4*>(&Ws[0][wr][wc]) = wv;
    __syncthreads();

    int buf = 0;
    for (int k0 = 0; k0 < K; k0 += 16) {
        const bool next = (k0 + 16) < K;
        if (next) {
            av = *reinterpret_cast<const float4*>(A + (size_t)ar * lda + k0 + 16 + ak);
            wv = *reinterpret_cast<const float4*>(W + (size_t)(k0 + 16 + wr) * N + ccol + wc);
        }
#pragma unroll
        for (int k = 0; k < 16; k++) {
            float4 a4 = *reinterpret_cast<const float4*>(&As[buf][k][ty * 4]);
            float4 w4 = *reinterpret_cast<const float4*>(&Ws[buf][k][tx * 4]);
            float ar_[4] = {a4.x, a4.y, a4.z, a4.w};
            float wr_[4] = {w4.x, w4.y, w4.z, w4.w};
#pragma unroll
            for (int i = 0; i < 4; i++)
#pragma unroll
                for (int j = 0; j < 4; j++)
                    acc[i][j] = fmaf(ar_[i], wr_[j], acc[i][j]);
        }
        if (next) {
            As[buf ^ 1][ak + 0][ar] = av.x; As[buf ^ 1][ak + 1][ar] = av.y;
            As[buf ^ 1][ak + 2][ar] = av.z; As[buf ^ 1][ak + 3][ar] = av.w;
            *reinterpret_cast<float4*>(&Ws[buf ^ 1][wr][wc]) = wv;
        }
        __syncthreads();
        buf ^= 1;
    }
    float b4[4];
#pragma unroll
    for (int j = 0; j < 4; j++) b4[j] = bias[ccol + tx * 4 + j];
#pragma unroll
    for (int i = 0; i < 4; i++) {
        float o[4];
#pragma unroll
        for (int j = 0; j < 4; j++) {
            float v = acc[i][j] + b4[j];
            if (act) v = (v >= 0.f) ? v : 0.01f * v;
            o[j] = v;
        }
        *reinterpret_cast<float4*>(C + (size_t)(ty * 4 + i) * N + ccol + tx * 4) =
            make_float4(o[0], o[1], o[2], o[3]);
    }
}

// ---------------------------------------------------------------------------
__global__ void bu_kernel(const float* __restrict__ in, const float* __restrict__ Bw)
{
    __shared__ float us[32][16];
    const int tid = threadIdx.x;
    const size_t r0 = (size_t)blockIdx.x * 32;
    float w[16];
#pragma unroll
    for (int k = 0; k < 16; k++) w[k] = Bw[k * 256 + tid];
#pragma unroll
    for (int i = tid; i < 32 * 16; i += 256) {
        int r = i >> 4, k = i & 15;
        us[r][k] = in[(r0 + r) * Din + 272 + k];
    }
    __syncthreads();
#pragma unroll 4
    for (int r = 0; r < 32; r++) {
        float acc = 0.f;
#pragma unroll
        for (int k = 0; k < 16; k++) acc = fmaf(us[r][k], w[k], acc);
        g_ZB[(r0 + r) * 256 + tid] = acc;
    }
}

__global__ void fold_kernel(const float* __restrict__ A)
{
    __shared__ float zs[256];
    const int b = blockIdx.x, j = threadIdx.x;
    zs[j] = g_z0[b * 256 + j];
    __syncthreads();
    float a0 = 0.f, a1 = 0.f, a2 = 0.f, a3 = 0.f;
    for (int k = 0; k < 256; k += 4) {
        a0 = fmaf(zs[k + 0], A[(k + 0) * 256 + j], a0);
        a1 = fmaf(zs[k + 1], A[(k + 1) * 256 + j], a1);
        a2 = fmaf(zs[k + 2], A[(k + 2) * 256 + j], a2);
        a3 = fmaf(zs[k + 3], A[(k + 3) * 256 + j], a3);
    }
    g_ZB[(size_t)b * Tt * 256 + j] += (a0 + a1) + (a2 + a3);
}

__global__ void powinit_kernel(const float* __restrict__ A)
{
    const int i = blockIdx.x * 256 + threadIdx.x;
    g_Apow[65536 + i] = A[i];
}

__global__ __launch_bounds__(256)
void pow_gemm(int half)
{
    const int q = blockIdx.z + 1;
    const float* S1 = g_Apow + (size_t)half * 65536;
    const float* S2 = g_Apow + (size_t)q * 65536;
    float* D = g_Apow + (size_t)(half + q) * 65536;
    const int ib = blockIdx.y * 64, jb = blockIdx.x * 64;
    __shared__ __align__(16) float As[16][64];
    __shared__ __align__(16) float Bs[16][64];
    const int tid = threadIdx.x;
    const int ar = tid >> 2, ak = (tid & 3) * 4;
    const int wr = tid >> 4, wc = (tid & 15) * 4;
    const int ty = tid >> 4, tx = tid & 15;
    float acc[4][4] = {};
    for (int k0 = 0; k0 < 256; k0 += 16) {
        float4 av = *reinterpret_cast<const float4*>(S1 + (size_t)(ib + ar) * 256 + k0 + ak);
        As[ak + 0][ar] = av.x; As[ak + 1][ar] = av.y;
        As[ak + 2][ar] = av.z; As[ak + 3][ar] = av.w;
        *reinterpret_cast<float4*>(&Bs[wr][wc]) =
            *reinterpret_cast<const float4*>(S2 + (size_t)(k0 + wr) * 256 + jb + wc);
        __syncthreads();
#pragma unroll
        for (int k = 0; k < 16; k++) {
            float4 a4 = *reinterpret_cast<const float4*>(&As[k][ty * 4]);
            float4 w4 = *reinterpret_cast<const float4*>(&Bs[k][tx * 4]);
            float ar_[4] = {a4.x, a4.y, a4.z, a4.w};
            float wr_[4] = {w4.x, w4.y, w4.z, w4.w};
#pragma unroll
            for (int i = 0; i < 4; i++)
#pragma unroll
                for (int j = 0; j < 4; j++)
                    acc[i][j] = fmaf(ar_[i], wr_[j], acc[i][j]);
        }
        __syncthreads();
    }
#pragma unroll
    for (int i = 0; i < 4; i++)
        *reinterpret_cast<float4*>(D + (size_t)(ib + ty * 4 + i) * 256 + jb + tx * 4) =
            make_float4(acc[i][0], acc[i][1], acc[i][2], acc[i][3]);
}

__global__ __launch_bounds__(256)
void local_step2(const float* __restrict__ A, int s)
{
    __shared__ __align__(16) float Zs[2][16][64];
    __shared__ __align__(16) float As_[2][16][64];
    const int c = blockIdx.y;
    const int jb = blockIdx.x * 64;
    const int tid = threadIdx.x;
    const int ty = tid >> 4, tx = tid & 15;
    const int zr = tid >> 2, zk = (tid & 3) * 4;
    const int ar = tid >> 4, ac = (tid & 15) * 4;
    const int tprev = c * CHUNK + s - 1;
    const float* zprev = g_ZB + ((size_t)zr * Tt + tprev) * 256;
    float acc[4][4] = {};

    {
        float4 zv = *reinterpret_cast<const float4*>(zprev + zk);
        Zs[0][zk + 0][zr] = zv.x; Zs[0][zk + 1][zr] = zv.y;
        Zs[0][zk + 2][zr] = zv.z; Zs[0][zk + 3][zr] = zv.w;
        cpa16(&As_[0][ar][ac], A + (size_t)ar * 256 + jb + ac);
        cpa_commit();
        cpa_wait0();
        __syncthreads();
    }
    int buf = 0;
    for (int k0 = 0; k0 < 256; k0 += 16) {
        const bool next = (k0 + 16) < 256;
        float4 zv;
        if (next) {
            zv = *reinterpret_cast<const float4*>(zprev + k0 + 16 + zk);
            cpa16(&As_[buf ^ 1][ar][ac], A + (size_t)(k0 + 16 + ar) * 256 + jb + ac);
            cpa_commit();
        }
#pragma unroll
        for (int k = 0; k < 16; k++) {
            float4 z4 = *reinterpret_cast<const float4*>(&Zs[buf][k][ty * 4]);
            float4 a4 = *reinterpret_cast<const float4*>(&As_[buf][k][tx * 4]);
            float zrr[4] = {z4.x, z4.y, z4.z, z4.w};
            float arr[4] = {a4.x, a4.y, a4.z, a4.w};
#pragma unroll
            for (int i = 0; i < 4; i++)
#pragma unroll
                for (int j = 0; j < 4; j++)
                    acc[i][j] = fmaf(zrr[i], arr[j], acc[i][j]);
        }
        if (next) {
            Zs[buf ^ 1][zk + 0][zr] = zv.x; Zs[buf ^ 1][zk + 1][zr] = zv.y;
            Zs[buf ^ 1][zk + 2][zr] = zv.z; Zs[buf ^ 1][zk + 3][zr] = zv.w;
        }
        cpa_wait0();
        __syncthreads();
        buf ^= 1;
    }
    const int tcur = c * CHUNK + s;
#pragma unroll
    for (int i = 0; i < 4; i++) {
        float4* p = reinterpret_cast<float4*>(
            g_ZB + ((size_t)(ty * 4 + i) * Tt + tcur) * 256 + jb + tx * 4);
        float4 o = *p;
        o.x += acc[i][0]; o.y += acc[i][1]; o.z += acc[i][2]; o.w += acc[i][3];
        *p = o;
    }
}

__global__ void carry_chain()
{
    const int bg = blockIdx.x * 2;
    const int j = threadIdx.x;
    __shared__ float cp0[256], cp1[256];
    cp0[j] = 0.f; cp1[j] = 0.f;
    __syncthreads();
    const float* A32 = g_Apow + (size_t)32 * 65536;
    for (int c = 1; c < NCHUNK; c++) {
        float a0 = g_ZB[((size_t)bg * Tt + c * CHUNK - 1) * 256 + j];
        float a1 = g_ZB[((size_t)(bg + 1) * Tt + c * CHUNK - 1) * 256 + j];
#pragma unroll 4
        for (int k = 0; k < 256; k++) {
            float w = A32[(size_t)k * 256 + j];
            a0 = fmaf(cp0[k], w, a0);
            a1 = fmaf(cp1[k], w, a1);
        }
        __syncthreads();
        cp0[j] = a0; cp1[j] = a1;
        g_carry[((size_t)c * 64 + bg) * 256 + j] = a0;
        g_carry[((size_t)c * 64 + bg + 1) * 256 + j] = a1;
        __syncthreads();
    }
}

// ---------------------------------------------------------------------------
extern "C" void kernel_launch(void* const* d_in, const int* in_sizes, int n_in,
                              void* d_out, int out_size)
{
    const float* in  = (const float*)d_in[0];
    const float* ew1 = (const float*)d_in[1];
    const float* eb1 = (const float*)d_in[2];
    const float* ew2 = (const float*)d_in[3];
    const float* eb2 = (const float*)d_in[4];
    const float* ew3 = (const float*)d_in[5];
    const float* eb3 = (const float*)d_in[6];
    const float* Aw  = (const float*)d_in[7];
    const float* Bw  = (const float*)d_in[8];
    const float* dw1 = (const float*)d_in[9];
    const float* db1 = (const float*)d_in[10];
    const float* dw2 = (const float*)d_in[11];
    const float* db2 = (const float*)d_in[12];
    const float* dw3 = (const float*)d_in[13];
    const float* db3 = (const float*)d_in[14];
    float* out = (float*)d_out;

    void *pzb, *ph1, *ph2, *ph1e, *ph2e, *pz0, *pcar, *papw;
    void *pazh, *pazl, *pw1h, *pw1l, *pw2h, *pw2l, *pw3h, *pw3l;
    cudaGetSymbolAddress(&pzb, g_ZB);
    cudaGetSymbolAddress(&ph1, g_H1);
    cudaGetSymbolAddress(&ph2, g_H2);
    cudaGetSymbolAddress(&ph1e, g_h1e);
    cudaGetSymbolAddress(&ph2e, g_h2e);
    cudaGetSymbolAddress(&pz0, g_z0);
    cudaGetSymbolAddress(&pcar, g_carry);
    cudaGetSymbolAddress(&papw, g_Apow);
    cudaGetSymbolAddress(&pazh, g_AZh);
    cudaGetSymbolAddress(&pazl, g_AZl);
    cudaGetSymbolAddress(&pw1h, g_W1h);
    cudaGetSymbolAddress(&pw1l, g_W1l);
    cudaGetSymbolAddress(&pw2h, g_W2h);
    cudaGetSymbolAddress(&pw2l, g_W2l);
    cudaGetSymbolAddress(&pw3h, g_W3h);
    cudaGetSymbolAddress(&pw3l, g_W3l);
    float* zb   = (float*)pzb;
    float* h1e  = (float*)ph1e;
    float* h2e  = (float*)ph2e;
    float* z0   = (float*)pz0;
    float* car1 = (float*)pcar + (size_t)64 * 256;
    float* apw1 = (float*)papw + 65536;
    __nv_bfloat16* AZh = (__nv_bfloat16*)pazh;
    __nv_bfloat16* AZl = (__nv_bfloat16*)pazl;
    __nv_bfloat16* B1h = (__nv_bfloat16*)ph1;
    __nv_bfloat16* B1l = B1h + (size_t)NROWS * ENCD;
    __nv_bfloat16* B2h = (__nv_bfloat16*)ph2;
    __nv_bfloat16* B2l = B2h + (size_t)NROWS * ENCD;

    cudaFuncSetAttribute(mma_gemm<1, 1>, cudaFuncAttributeMaxDynamicSharedMemorySize, MMA_SMEM);
    cudaFuncSetAttribute(mma_gemm<0, 0>, cudaFuncAttributeMaxDynamicSharedMemorySize, MMA_SMEM);

    // Bu for all t (writes all of g_ZB)
    bu_kernel<<<NROWS / 32, 256>>>(in, Bw);

    // weight splits (independent; run early)
    split_w<<<(256 * 512 + 255) / 256, 256>>>(dw1, 256, 512, (__nv_bfloat16*)pw1h, (__nv_bfloat16*)pw1l);
    split_w<<<(512 * 512 + 255) / 256, 256>>>(dw2, 512, 512, (__nv_bfloat16*)pw2h, (__nv_bfloat16*)pw2l);
    split_w<<<(512 * 256 + 255) / 256, 256>>>(dw3, 512, 256, (__nv_bfloat16*)pw3h, (__nv_bfloat16*)pw3l);

    // encoder at t=0 only
    gemm_m64<<<ENCD / 64, 256>>>(in, (long long)Tt * Din, ew1, eb1, h1e, ENCD, 256, 1);
    gemm_m64<<<ENCD / 64, 256>>>(h1e, ENCD, ew2, eb2, h2e, ENCD, ENCD, 1);
    gemm_m64<<<LAT / 64, 256>>>(h2e, ENCD, ew3, eb3, z0, LAT, ENCD, 1);
    fold_kernel<<<64, 256>>>(Aw);

    // powers A^1..A^32
    powinit_kernel<<<256, 256>>>(Aw);
    for (int half = 1; half <= 16; half <<= 1)
        pow_gemm<<<dim3(4, 4, half), 256>>>(half);

    // chunk-local scan
    for (int s = 1; s < CHUNK; s++)
        local_step2<<<dim3(4, NCHUNK), 256>>>(Aw, s);

    // carry chain
    carry_chain<<<32, 256>>>();

    // fix as one GEMM: carry(1984x256) @ [A^1|..|A^32](256x8192), scatter += ZB
    gemm_pipe<1, 0><<<dim3(64, 16), 256>>>(car1, 256, apw1, nullptr, nullptr,
                                           1984, 8192, 256);

    // split finalized z into bf16 hi/lo
    split_f32<<<(NROWS * LAT / 4 + 255) / 256, 256>>>(zb, AZh, AZl, (size_t)NROWS * LAT);

    // decoder on tensor cores (warp mma, split-bf16, fp32 accumulate)
    mma_gemm<1, 1><<<dim3(ENCD / 128, NROWS / 128), 256, MMA_SMEM>>>(
        AZh, AZl, (__nv_bfloat16*)pw1h, (__nv_bfloat16*)pw1l, db1,
        B1h, B1l, nullptr, ENCD, LAT);
    mma_gemm<1, 1><<<dim3(ENCD / 128, NROWS / 128), 256, MMA_SMEM>>>(
        B1h, B1l, (__nv_bfloat16*)pw2h, (__nv_bfloat16*)pw2l, db2,
        B2h, B2l, nullptr, ENCD, ENCD);
    mma_gemm<0, 0><<<dim3(LAT / 128, NROWS / 128), 256, MMA_SMEM>>>(
        B2h, B2l, (__nv_bfloat16*)pw3h, (__nv_bfloat16*)pw3l, db3,
        nullptr, nullptr, out, LAT, ENCD);
}

// round 9
// speedup vs baseline: 1.9433x; 1.2762x over previous
#include <cuda_runtime.h>
#include <cuda_bf16.h>
#include <cstdint>

// ---------------------------------------------------------------------------
// HiroLRAN: encoder(t=0) -> rank-16 scan-as-GEMM -> decoder, mma.sync bf16
// split precision everywhere heavy. B=64, T=1024, LATENT=256, ENC=512, ACT=16.
//
// Scan algebra: z_{c,s} = local_{c,s} + carry_c @ A^{s+1}
//   local_{c,s} = sum_{j<=s} u_{c,j} @ (B A^{s-j})   (rank-16 -> ONE GEMM)
//   carry_0 = z0 (encoder), carry_c = carry_{c-1} @ A^32 + local_{c-1,31}
// ---------------------------------------------------------------------------

#define Bsz 64
#define Tt 1024
#define Din 288
#define LAT 256
#define ENCD 512
#define NROWS (Bsz * Tt)   // 65536
#define PADK 40            // padded K-stride (elements) for ldmatrix tiles

// scratch (device globals: no allocations allowed)
__device__ float g_ZB[(size_t)NROWS * LAT];
__device__ float g_H1[(size_t)NROWS * ENCD];     // aliased: B1 hi|lo bf16
__device__ float g_H2[(size_t)NROWS * ENCD];     // aliased: B2 hi|lo bf16
__device__ float g_Apow[33 * LAT * LAT];         // A^1..A^32 at idx 1..32
__device__ float g_carry[32 * Bsz * LAT];        // carries c=0..31
__device__ float g_h1e[Bsz * ENCD];
__device__ float g_h2e[Bsz * ENCD];
__device__ float g_z0[Bsz * LAT];
__device__ float g_G[32 * 16 * 256];             // G_r = B A^r
__device__ __nv_bfloat16 g_AZh[(size_t)NROWS * LAT];
__device__ __nv_bfloat16 g_AZl[(size_t)NROWS * LAT];
__device__ __nv_bfloat16 g_W1h[ENCD * LAT], g_W1l[ENCD * LAT];   // N x K
__device__ __nv_bfloat16 g_W2h[ENCD * ENCD], g_W2l[ENCD * ENCD];
__device__ __nv_bfloat16 g_W3h[LAT * ENCD], g_W3l[LAT * ENCD];
__device__ __nv_bfloat16 g_Uh[2048 * 512], g_Ul[2048 * 512];     // gathered u
__device__ __nv_bfloat16 g_Wlh[8192 * 512], g_Wll[8192 * 512];   // Toeplitz G
__device__ __nv_bfloat16 g_Wfh[8192 * 256], g_Wfl[8192 * 256];   // [A^1..A^32]
__device__ __nv_bfloat16 g_Ch[2048 * 256], g_Cl[2048 * 256];     // split carry

// ---- async copy helpers -----------------------------------------------------
__device__ __forceinline__ uint32_t smem_u32(const void* p) {
    return (uint32_t)__cvta_generic_to_shared(p);
}
__device__ __forceinline__ void cpa16s(uint32_t saddr, const void* gsrc) {
    asm volatile("cp.async.ca.shared.global [%0], [%1], 16;\n" :: "r"(saddr), "l"(gsrc));
}
__device__ __forceinline__ void cpa_commit() {
    asm volatile("cp.async.commit_group;\n");
}
__device__ __forceinline__ void cpa_wait0() {
    asm volatile("cp.async.wait_group 0;\n" ::: "memory");
}
__device__ __forceinline__ void cpa_wait1() {
    asm volatile("cp.async.wait_group 1;\n" ::: "memory");
}

// ---- warp-level mma helpers ---------------------------------------------------
__device__ __forceinline__ void ldsm4(uint32_t addr, uint32_t& r0, uint32_t& r1,
                                      uint32_t& r2, uint32_t& r3) {
    asm volatile("ldmatrix.sync.aligned.m8n8.x4.shared.b16 {%0,%1,%2,%3}, [%4];"
                 : "=r"(r0), "=r"(r1), "=r"(r2), "=r"(r3) : "r"(addr));
}
__device__ __forceinline__ void mma16816(float* c, const uint32_t* a,
                                         const uint32_t* b) {
    asm volatile(
        "mma.sync.aligned.m16n8k16.row.col.f32.bf16.bf16.f32 "
        "{%0,%1,%2,%3}, {%4,%5,%6,%7}, {%8,%9}, {%0,%1,%2,%3};"
        : "+f"(c[0]), "+f"(c[1]), "+f"(c[2]), "+f"(c[3])
        : "r"(a[0]), "r"(a[1]), "r"(a[2]), "r"(a[3]), "r"(b[0]), "r"(b[1]));
}

// ---------------------------------------------------------------------------
// mma.sync split-bf16 GEMM: C = act(Afull @ Wfull^T + bias)
// 128x128 CTA tile, 8 warps (2x4), warp tile 64x32, BK=32 double-buffered.
// 3 products per chunk: Ah*Bh + Ah*Bl + Al*Bh (fp32 accumulate).
// OUT: 0 = dense hi/lo bf16 out, 1 = dense fp32 out,
//      2 = scatter STORE fp32 -> g_ZB (local scan), 3 = scatter ADD (fix).
// Scatter mapping: row m -> (chunk c = m>>6, batch b = m&63);
//                  col n -> (s = n>>8, j = n&255); t = c*32+s.
// ---------------------------------------------------------------------------
#define STAGE_ELEMS (4 * 128 * PADK)           // 20480 bf16 per stage
#define MMA_SMEM (2 * STAGE_ELEMS * 2)         // 81920 bytes

template<int ACT, int OUT>
__global__ __launch_bounds__(256, 1)
void mma_gemm(const __nv_bfloat16* __restrict__ Ah, const __nv_bfloat16* __restrict__ Al,
              const __nv_bfloat16* __restrict__ Bh, const __nv_bfloat16* __restrict__ Bl,
              const float* __restrict__ bias,
              __nv_bfloat16* __restrict__ oHi, __nv_bfloat16* __restrict__ oLo,
              float* __restrict__ oF, int N, int K)
{
    extern __shared__ __align__(16) __nv_bfloat16 smem[];
    const int tid  = threadIdx.x;
    const int warp = tid >> 5;
    const int lane = tid & 31;
    const int crow = blockIdx.y * 128;
    const int ccol = blockIdx.x * 128;
    const int mo = (warp >> 2) * 64;
    const int no = (warp & 3) * 32;

    const __nv_bfloat16* gsrc[4] = {
        Ah + (size_t)crow * K, Al + (size_t)crow * K,
        Bh + (size_t)ccol * K, Bl + (size_t)ccol * K };

    auto load_chunk = [&](int s, int kc) {
#pragma unroll
        for (int q = 0; q < 4; q++) {
            const __nv_bfloat16* src = gsrc[q] + kc * 32;
            __nv_bfloat16* dstb = smem + s * STAGE_ELEMS + q * 128 * PADK;
#pragma unroll
            for (int t = 0; t < 2; t++) {
                int g = tid + t * 256;
                int row = g >> 2, c = g & 3;
                cpa16s(smem_u32(dstb + row * PADK + c * 8),
                       src + (size_t)row * K + c * 8);
            }
        }
        cpa_commit();
    };

    float acc[4][4][4];
#pragma unroll
    for (int i = 0; i < 4; i++)
#pragma unroll
        for (int j = 0; j < 4; j++)
#pragma unroll
            for (int v = 0; v < 4; v++) acc[i][j][v] = 0.f;

    const int nch = K / 32;
    load_chunk(0, 0);
    load_chunk(1, 1);

    const int a_rowsel = lane & 15;
    const int a_colsel = (lane >> 4) << 3;
    const int b_rowsel = ((lane >> 4) << 3) + (lane & 7);
    const int b_colsel = ((lane >> 3) & 1) << 3;

    for (int i = 0; i < nch; i++) {
        const int s = i & 1;
        if (i + 1 < nch) cpa_wait1(); else cpa_wait0();
        __syncthreads();
        const uint32_t stb = smem_u32(smem) + s * STAGE_ELEMS * 2;
        const uint32_t bAh = stb;
        const uint32_t bAl = stb + 128 * PADK * 2;
        const uint32_t bBh = stb + 2 * 128 * PADK * 2;
        const uint32_t bBl = stb + 3 * 128 * PADK * 2;
#pragma unroll
        for (int kk = 0; kk < 2; kk++) {
            const int kc = kk * 16;
            uint32_t a[4][4], b[4][2], bl[4][2];
#pragma unroll
            for (int it = 0; it < 4; it++) {
                int row = mo + it * 16 + a_rowsel;
                ldsm4(bAh + (row * PADK + kc + a_colsel) * 2,
                      a[it][0], a[it][1], a[it][2], a[it][3]);
            }
#pragma unroll
            for (int jj = 0; jj < 2; jj++) {
                int row = no + jj * 16 + b_rowsel;
                ldsm4(bBh + (row * PADK + kc + b_colsel) * 2,
                      b[2 * jj][0], b[2 * jj][1], b[2 * jj + 1][0], b[2 * jj + 1][1]);
            }
#pragma unroll
            for (int it = 0; it < 4; it++)
#pragma unroll
                for (int jt = 0; jt < 4; jt++) mma16816(acc[it][jt], a[it], b[jt]);
#pragma unroll
            for (int jj = 0; jj < 2; jj++) {
                int row = no + jj * 16 + b_rowsel;
                ldsm4(bBl + (row * PADK + kc + b_colsel) * 2,
                      bl[2 * jj][0], bl[2 * jj][1], bl[2 * jj + 1][0], bl[2 * jj + 1][1]);
            }
#pragma unroll
            for (int it = 0; it < 4; it++)
#pragma unroll
                for (int jt = 0; jt < 4; jt++) mma16816(acc[it][jt], a[it], bl[jt]);
#pragma unroll
            for (int it = 0; it < 4; it++) {
                int row = mo + it * 16 + a_rowsel;
                ldsm4(bAl + (row * PADK + kc + a_colsel) * 2,
                      a[it][0], a[it][1], a[it][2], a[it][3]);
            }
#pragma unroll
            for (int it = 0; it < 4; it++)
#pragma unroll
                for (int jt = 0; jt < 4; jt++) mma16816(acc[it][jt], a[it], b[jt]);
        }
        __syncthreads();
        if (i + 2 < nch) load_chunk(s, i + 2);
    }

#pragma unroll
    for (int it = 0; it < 4; it++) {
#pragma unroll
        for (int jt = 0; jt < 4; jt++) {
            const int r0 = crow + mo + it * 16 + (lane >> 2);
            const int gc = ccol + no + jt * 8 + (lane & 3) * 2;
            float v00 = acc[it][jt][0], v01 = acc[it][jt][1];
            float v10 = acc[it][jt][2], v11 = acc[it][jt][3];
            if (OUT <= 1) {
                const float b0 = bias[gc], b1 = bias[gc + 1];
                v00 += b0; v01 += b1; v10 += b0; v11 += b1;
                if (ACT) {
                    v00 = (v00 >= 0.f) ? v00 : 0.01f * v00;
                    v01 = (v01 >= 0.f) ? v01 : 0.01f * v01;
                    v10 = (v10 >= 0.f) ? v10 : 0.01f * v10;
                    v11 = (v11 >= 0.f) ? v11 : 0.01f * v11;
                }
            }
            if (OUT == 0) {
                __nv_bfloat16 h00 = __float2bfloat16(v00), h01 = __float2bfloat16(v01);
                __nv_bfloat16 h10 = __float2bfloat16(v10), h11 = __float2bfloat16(v11);
                *reinterpret_cast<__nv_bfloat162*>(oHi + (size_t)r0 * N + gc) =
                    __nv_bfloat162(h00, h01);
                *reinterpret_cast<__nv_bfloat162*>(oHi + (size_t)(r0 + 8) * N + gc) =
                    __nv_bfloat162(h10, h11);
                *reinterpret_cast<__nv_bfloat162*>(oLo + (size_t)r0 * N + gc) =
                    __nv_bfloat162(__float2bfloat16(v00 - __bfloat162float(h00)),
                                   __float2bfloat16(v01 - __bfloat162float(h01)));
                *reinterpret_cast<__nv_bfloat162*>(oLo + (size_t)(r0 + 8) * N + gc) =
                    __nv_bfloat162(__float2bfloat16(v10 - __bfloat162float(h10)),
                                   __float2bfloat16(v11 - __bfloat162float(h11)));
            } else if (OUT == 1) {
                *reinterpret_cast<float2*>(oF + (size_t)r0 * N + gc) =
                    make_float2(v00, v01);
                *reinterpret_cast<float2*>(oF + (size_t)(r0 + 8) * N + gc) =
                    make_float2(v10, v11);
            } else {
                const int s  = gc >> 8;
                const int j  = gc & 255;
                const int c0 = r0 >> 6;           // same 64-block for r0 and r0+8
                const int b0r = r0 & 63;
                const int t = c0 * 32 + s;
                float2* p0 = reinterpret_cast<float2*>(
                    &g_ZB[((size_t)b0r * Tt + t) * 256 + j]);
                float2* p1 = reinterpret_cast<float2*>(
                    &g_ZB[((size_t)((b0r + 8) & 63) * Tt + ((((r0 + 8) >> 6)) * 32 + s)) * 256 + j]);
                if (OUT == 2) {
                    *p0 = make_float2(v00, v01);
                    *p1 = make_float2(v10, v11);
                } else {
                    float2 o0 = *p0, o1 = *p1;
                    o0.x += v00; o0.y += v01; o1.x += v10; o1.y += v11;
                    *p0 = o0; *p1 = o1;
                }
            }
        }
    }
}

// split fp32 -> (hi, lo) bf16, same layout
__global__ void split_f32(const float* __restrict__ src,
                          __nv_bfloat16* __restrict__ hi,
                          __nv_bfloat16* __restrict__ lo, size_t n)
{
    size_t i = ((size_t)blockIdx.x * blockDim.x + threadIdx.x) * 4;
    if (i >= n) return;
    float4 v = *reinterpret_cast<const float4*>(src + i);
    __nv_bfloat16 h0 = __float2bfloat16(v.x), h1 = __float2bfloat16(v.y);
    __nv_bfloat16 h2 = __float2bfloat16(v.z), h3 = __float2bfloat16(v.w);
    reinterpret_cast<__nv_bfloat162*>(hi + i)[0] = __nv_bfloat162(h0, h1);
    reinterpret_cast<__nv_bfloat162*>(hi + i)[1] = __nv_bfloat162(h2, h3);
    reinterpret_cast<__nv_bfloat162*>(lo + i)[0] = __nv_bfloat162(
        __float2bfloat16(v.x - __bfloat162float(h0)),
        __float2bfloat16(v.y - __bfloat162float(h1)));
    reinterpret_cast<__nv_bfloat162*>(lo + i)[1] = __nv_bfloat162(
        __float2bfloat16(v.z - __bfloat162float(h2)),
        __float2bfloat16(v.w - __bfloat162float(h3)));
}

// split + transpose weights: W (K x N fp32) -> hi/lo (N x K bf16)
__global__ void split_w(const float* __restrict__ W, int K, int N,
                        __nv_bfloat16* __restrict__ hi, __nv_bfloat16* __restrict__ lo)
{
    int idx = blockIdx.x * 256 + threadIdx.x;
    if (idx >= K * N) return;
    int k = idx / N, n = idx % N;
    float v = W[idx];
    __nv_bfloat16 h = __float2bfloat16(v);
    hi[(size_t)n * K + k] = h;
    lo[(size_t)n * K + k] = __float2bfloat16(v - __bfloat162float(h));
}

// gather u slices -> U[2048 x 512] split bf16. row m=(c*64+b), col k=(j*16+i)
__global__ void gatherU(const float* __restrict__ in)
{
    int idx = blockIdx.x * 256 + threadIdx.x;
    if (idx >= 2048 * 512) return;
    int m = idx >> 9, k = idx & 511;
    int c = m >> 6, b = m & 63;
    int j = k >> 4, i = k & 15;
    float v = in[((size_t)b * Tt + c * 32 + j) * Din + 272 + i];
    __nv_bfloat16 h = __float2bfloat16(v);
    g_Uh[idx] = h;
    g_Ul[idx] = __float2bfloat16(v - __bfloat162float(h));
}

// G_r = B_w @ A^r (r=0..31; G_0 = B_w)
__global__ void buildG(const float* __restrict__ Bw)
{
    const int r = blockIdx.x;
    const int n = threadIdx.x;
    if (r == 0) {
        for (int i = 0; i < 16; i++)
            g_G[i * 256 + n] = Bw[i * 256 + n];
        return;
    }
    const float* Ar = g_Apow + (size_t)r * 65536;
    float acc[16];
#pragma unroll
    for (int i = 0; i < 16; i++) acc[i] = 0.f;
    for (int m = 0; m < 256; m++) {
        float a = Ar[m * 256 + n];
#pragma unroll
        for (int i = 0; i < 16; i++)
            acc[i] = fmaf(Bw[i * 256 + m], a, acc[i]);
    }
#pragma unroll
    for (int i = 0; i < 16; i++)
        g_G[(r * 16 + i) * 256 + n] = acc[i];
}

// Wlocal[n=(s*256+col)][k=(j*16+i)] = (s>=j) ? G_{s-j}[i][col] : 0
__global__ void buildWlocal()
{
    int idx = blockIdx.x * 256 + threadIdx.x;
    if (idx >= 8192 * 512) return;
    int n = idx >> 9, k = idx & 511;
    int s = n >> 8, col = n & 255, j = k >> 4, i = k & 15;
    int r = s - j;
    float v = (r >= 0) ? g_G[(r * 16 + i) * 256 + col] : 0.f;
    __nv_bfloat16 h = __float2bfloat16(v);
    g_Wlh[idx] = h;
    g_Wll[idx] = __float2bfloat16(v - __bfloat162float(h));
}

// Wfix[n=(s*256+col)][k] = A^{s+1}[k][col]
__global__ void buildWfix()
{
    int idx = blockIdx.x * 256 + threadIdx.x;
    if (idx >= 8192 * 256) return;
    int n = idx >> 8, k = idx & 255;
    int s = n >> 8, col = n & 255;
    float v = g_Apow[(size_t)(s + 1) * 65536 + k * 256 + col];
    __nv_bfloat16 h = __float2bfloat16(v);
    g_Wfh[idx] = h;
    g_Wfl[idx] = __float2bfloat16(v - __bfloat162float(h));
}

// ---------------------------------------------------------------------------
// Small-M GEMM (encoder, M=64)
// ---------------------------------------------------------------------------
__global__ __launch_bounds__(256)
void gemm_m64(const float* __restrict__ A, long long lda,
              const float* __restrict__ W,
              const float* __restrict__ bias,
              float* __restrict__ C,
              int N, int K, int act)
{
    __shared__ __align__(16) float As[2][16][64];
    __shared__ __align__(16) float Ws[2][16][64];
    const int tid  = threadIdx.x;
    const int ccol = blockIdx.x * 64;
    const int ar = tid >> 2, ak = (tid & 3) * 4;
    const int wr = tid >> 4, wc = (tid & 15) * 4;
    const int ty = tid >> 4, tx = tid & 15;
    float acc[4][4] = {};

    float4 av = *reinterpret_cast<const float4*>(A + (size_t)ar * lda + ak);
    float4 wv = *reinterpret_cast<const float4*>(W + (size_t)wr * N + ccol + wc);
    As[0][ak + 0][ar] = av.x; As[0][ak + 1][ar] = av.y;
    As[0][ak + 2][ar] = av.z; As[0][ak + 3][ar] = av.w;
    *reinterpret_cast<float4*>(&Ws[0][wr][wc]) = wv;
    __syncthreads();

    int buf = 0;
    for (int k0 = 0; k0 < K; k0 += 16) {
        const bool next = (k0 + 16) < K;
        if (next) {
            av = *reinterpret_cast<const float4*>(A + (size_t)ar * lda + k0 + 16 + ak);
            wv = *reinterpret_cast<const float4*>(W + (size_t)(k0 + 16 + wr) * N + ccol + wc);
        }
#pragma unroll
        for (int k = 0; k < 16; k++) {
            float4 a4 = *reinterpret_cast<const float4*>(&As[buf][k][ty * 4]);
            float4 w4 = *reinterpret_cast<const float4*>(&Ws[buf][k][tx * 4]);
            float ar_[4] = {a4.x, a4.y, a4.z, a4.w};
            float wr_[4] = {w4.x, w4.y, w4.z, w4.w};
#pragma unroll
            for (int i = 0; i < 4; i++)
#pragma unroll
                for (int j = 0; j < 4; j++)
                    acc[i][j] = fmaf(ar_[i], wr_[j], acc[i][j]);
        }
        if (next) {
            As[buf ^ 1][ak + 0][ar] = av.x; As[buf ^ 1][ak + 1][ar] = av.y;
            As[buf ^ 1][ak + 2][ar] = av.z; As[buf ^ 1][ak + 3][ar] = av.w;
            *reinterpret_cast<float4*>(&Ws[buf ^ 1][wr][wc]) = wv;
        }
        __syncthreads();
        buf ^= 1;
    }
    float b4[4];
#pragma unroll
    for (int j = 0; j < 4; j++) b4[j] = bias[ccol + tx * 4 + j];
#pragma unroll
    for (int i = 0; i < 4; i++) {
        float o[4];
#pragma unroll
        for (int j = 0; j < 4; j++) {
            float v = acc[i][j] + b4[j];
            if (act) v = (v >= 0.f) ? v : 0.01f * v;
            o[j] = v;
        }
        *reinterpret_cast<float4*>(C + (size_t)(ty * 4 + i) * N + ccol + tx * 4) =
            make_float4(o[0], o[1], o[2], o[3]);
    }
}

// Apow[1] = A
__global__ void powinit_kernel(const float* __restrict__ A)
{
    const int i = blockIdx.x * 256 + threadIdx.x;
    g_Apow[65536 + i] = A[i];
}

// Apow[half+q] = Apow[half] @ Apow[q], q = blockIdx.z+1
__global__ __launch_bounds__(256)
void pow_gemm(int half)
{
    const int q = blockIdx.z + 1;
    const float* S1 = g_Apow + (size_t)half * 65536;
    const float* S2 = g_Apow + (size_t)q * 65536;
    float* D = g_Apow + (size_t)(half + q) * 65536;
    const int ib = blockIdx.y * 64, jb = blockIdx.x * 64;
    __shared__ __align__(16) float As[16][64];
    __shared__ __align__(16) float Bs[16][64];
    const int tid = threadIdx.x;
    const int ar = tid >> 2, ak = (tid & 3) * 4;
    const int wr = tid >> 4, wc = (tid & 15) * 4;
    const int ty = tid >> 4, tx = tid & 15;
    float acc[4][4] = {};
    for (int k0 = 0; k0 < 256; k0 += 16) {
        float4 av = *reinterpret_cast<const float4*>(S1 + (size_t)(ib + ar) * 256 + k0 + ak);
        As[ak + 0][ar] = av.x; As[ak + 1][ar] = av.y;
        As[ak + 2][ar] = av.z; As[ak + 3][ar] = av.w;
        *reinterpret_cast<float4*>(&Bs[wr][wc]) =
            *reinterpret_cast<const float4*>(S2 + (size_t)(k0 + wr) * 256 + jb + wc);
        __syncthreads();
#pragma unroll
        for (int k = 0; k < 16; k++) {
            float4 a4 = *reinterpret_cast<const float4*>(&As[k][ty * 4]);
            float4 w4 = *reinterpret_cast<const float4*>(&Bs[k][tx * 4]);
            float ar_[4] = {a4.x, a4.y, a4.z, a4.w};
            float wr_[4] = {w4.x, w4.y, w4.z, w4.w};
#pragma unroll
            for (int i = 0; i < 4; i++)
#pragma unroll
                for (int j = 0; j < 4; j++)
                    acc[i][j] = fmaf(ar_[i], wr_[j], acc[i][j]);
        }
        __syncthreads();
    }
#pragma unroll
    for (int i = 0; i < 4; i++)
        *reinterpret_cast<float4*>(D + (size_t)(ib + ty * 4 + i) * 256 + jb + tx * 4) =
            make_float4(acc[i][0], acc[i][1], acc[i][2], acc[i][3]);
}

// carry chain: 64 blocks (1 batch each); carry_0 = z0;
// carry_c = carry_{c-1} @ A^32 + local_{c-1,31} (g_ZB holds pure locals here)
__global__ void carry_chain64(const float* __restrict__ z0)
{
    const int b = blockIdx.x;
    const int j = threadIdx.x;
    __shared__ float cp[256];
    float cur = z0[b * 256 + j];
    cp[j] = cur;
    g_carry[(size_t)b * 256 + j] = cur;
    __syncthreads();
    const float* A32 = g_Apow + (size_t)32 * 65536;
    for (int c = 1; c < 32; c++) {
        float a = g_ZB[((size_t)b * Tt + c * 32 - 1) * 256 + j];
#pragma unroll 8
        for (int k = 0; k < 256; k++)
            a = fmaf(cp[k], A32[(size_t)k * 256 + j], a);
        __syncthreads();
        cp[j] = a;
        g_carry[((size_t)c * 64 + b) * 256 + j] = a;
        __syncthreads();
    }
}

// ---------------------------------------------------------------------------
extern "C" void kernel_launch(void* const* d_in, const int* in_sizes, int n_in,
                              void* d_out, int out_size)
{
    const float* in  = (const float*)d_in[0];
    const float* ew1 = (const float*)d_in[1];
    const float* eb1 = (const float*)d_in[2];
    const float* ew2 = (const float*)d_in[3];
    const float* eb2 = (const float*)d_in[4];
    const float* ew3 = (const float*)d_in[5];
    const float* eb3 = (const float*)d_in[6];
    const float* Aw  = (const float*)d_in[7];
    const float* Bw  = (const float*)d_in[8];
    const float* dw1 = (const float*)d_in[9];
    const float* db1 = (const float*)d_in[10];
    const float* dw2 = (const float*)d_in[11];
    const float* db2 = (const float*)d_in[12];
    const float* dw3 = (const float*)d_in[13];
    const float* db3 = (const float*)d_in[14];
    float* out = (float*)d_out;

    void *pzb, *ph1, *ph2, *ph1e, *ph2e, *pz0, *pcar;
    void *pazh, *pazl, *pw1h, *pw1l, *pw2h, *pw2l, *pw3h, *pw3l;
    void *puh, *pul, *pwlh, *pwll, *pwfh, *pwfl, *pch, *pcl;
    cudaGetSymbolAddress(&pzb, g_ZB);
    cudaGetSymbolAddress(&ph1, g_H1);
    cudaGetSymbolAddress(&ph2, g_H2);
    cudaGetSymbolAddress(&ph1e, g_h1e);
    cudaGetSymbolAddress(&ph2e, g_h2e);
    cudaGetSymbolAddress(&pz0, g_z0);
    cudaGetSymbolAddress(&pcar, g_carry);
    cudaGetSymbolAddress(&pazh, g_AZh);
    cudaGetSymbolAddress(&pazl, g_AZl);
    cudaGetSymbolAddress(&pw1h, g_W1h);
    cudaGetSymbolAddress(&pw1l, g_W1l);
    cudaGetSymbolAddress(&pw2h, g_W2h);
    cudaGetSymbolAddress(&pw2l, g_W2l);
    cudaGetSymbolAddress(&pw3h, g_W3h);
    cudaGetSymbolAddress(&pw3l, g_W3l);
    cudaGetSymbolAddress(&puh, g_Uh);
    cudaGetSymbolAddress(&pul, g_Ul);
    cudaGetSymbolAddress(&pwlh, g_Wlh);
    cudaGetSymbolAddress(&pwll, g_Wll);
    cudaGetSymbolAddress(&pwfh, g_Wfh);
    cudaGetSymbolAddress(&pwfl, g_Wfl);
    cudaGetSymbolAddress(&pch, g_Ch);
    cudaGetSymbolAddress(&pcl, g_Cl);
    float* zb   = (float*)pzb;
    float* h1e  = (float*)ph1e;
    float* h2e  = (float*)ph2e;
    float* z0   = (float*)pz0;
    float* car  = (float*)pcar;
    __nv_bfloat16* AZh = (__nv_bfloat16*)pazh;
    __nv_bfloat16* AZl = (__nv_bfloat16*)pazl;
    __nv_bfloat16* B1h = (__nv_bfloat16*)ph1;
    __nv_bfloat16* B1l = B1h + (size_t)NROWS * ENCD;
    __nv_bfloat16* B2h = (__nv_bfloat16*)ph2;
    __nv_bfloat16* B2l = B2h + (size_t)NROWS * ENCD;

    cudaFuncSetAttribute(mma_gemm<1, 0>, cudaFuncAttributeMaxDynamicSharedMemorySize, MMA_SMEM);
    cudaFuncSetAttribute(mma_gemm<0, 1>, cudaFuncAttributeMaxDynamicSharedMemorySize, MMA_SMEM);
    cudaFuncSetAttribute(mma_gemm<0, 2>, cudaFuncAttributeMaxDynamicSharedMemorySize, MMA_SMEM);
    cudaFuncSetAttribute(mma_gemm<0, 3>, cudaFuncAttributeMaxDynamicSharedMemorySize, MMA_SMEM);

    // A powers (needed by G, Wfix, carry chain)
    powinit_kernel<<<256, 256>>>(Aw);
    for (int half = 1; half <= 16; half <<= 1)
        pow_gemm<<<dim3(4, 4, half), 256>>>(half);

    // encoder at t=0 only -> z0 (= carry_0)
    gemm_m64<<<ENCD / 64, 256>>>(in, (long long)Tt * Din, ew1, eb1, h1e, ENCD, 256, 1);
    gemm_m64<<<ENCD / 64, 256>>>(h1e, ENCD, ew2, eb2, h2e, ENCD, ENCD, 1);
    gemm_m64<<<LAT / 64, 256>>>(h2e, ENCD, ew3, eb3, z0, LAT, ENCD, 1);

    // operand builds
    gatherU<<<(2048 * 512) / 256, 256>>>(in);
    buildG<<<32, 256>>>(Bw);
    buildWlocal<<<(8192 * 512) / 256, 256>>>();
    buildWfix<<<(8192 * 256) / 256, 256>>>();
    split_w<<<(256 * 512 + 255) / 256, 256>>>(dw1, 256, 512, (__nv_bfloat16*)pw1h, (__nv_bfloat16*)pw1l);
    split_w<<<(512 * 512 + 255) / 256, 256>>>(dw2, 512, 512, (__nv_bfloat16*)pw2h, (__nv_bfloat16*)pw2l);
    split_w<<<(512 * 256 + 255) / 256, 256>>>(dw3, 512, 256, (__nv_bfloat16*)pw3h, (__nv_bfloat16*)pw3l);

    // ONE GEMM for the entire chunk-local scan: U @ Wlocal -> g_ZB (store)
    mma_gemm<0, 2><<<dim3(64, 16), 256, MMA_SMEM>>>(
        (__nv_bfloat16*)puh, (__nv_bfloat16*)pul,
        (__nv_bfloat16*)pwlh, (__nv_bfloat16*)pwll,
        nullptr, nullptr, nullptr, nullptr, 8192, 512);

    // carry chain (single launch), then split carries
    carry_chain64<<<64, 256>>>(z0);
    split_f32<<<(2048 * 256 / 4 + 255) / 256, 256>>>(
        car, (__nv_bfloat16*)pch, (__nv_bfloat16*)pcl, (size_t)2048 * 256);

    // fix GEMM: carry @ [A^1..A^32] -> scatter-add into g_ZB (all 32 chunks)
    mma_gemm<0, 3><<<dim3(64, 16), 256, MMA_SMEM>>>(
        (__nv_bfloat16*)pch, (__nv_bfloat16*)pcl,
        (__nv_bfloat16*)pwfh, (__nv_bfloat16*)pwfl,
        nullptr, nullptr, nullptr, nullptr, 8192, 256);

    // split finalized z into bf16 hi/lo
    split_f32<<<(NROWS * LAT / 4 + 255) / 256, 256>>>(zb, AZh, AZl, (size_t)NROWS * LAT);

    // decoder (tensor cores, split-bf16)
    mma_gemm<1, 0><<<dim3(ENCD / 128, NROWS / 128), 256, MMA_SMEM>>>(
        AZh, AZl, (__nv_bfloat16*)pw1h, (__nv_bfloat16*)pw1l, db1,
        B1h, B1l, nullptr, ENCD, LAT);
    mma_gemm<1, 0><<<dim3(ENCD / 128, NROWS / 128), 256, MMA_SMEM>>>(
        B1h, B1l, (__nv_bfloat16*)pw2h, (__nv_bfloat16*)pw2l, db2,
        B2h, B2l, nullptr, ENCD, ENCD);
    mma_gemm<0, 1><<<dim3(LAT / 128, NROWS / 128), 256, MMA_SMEM>>>(
        B2h, B2l, (__nv_bfloat16*)pw3h, (__nv_bfloat16*)pw3l, db3,
        nullptr, nullptr, out, LAT, ENCD);
}